// round 10
// baseline (speedup 1.0000x reference)
#include <cuda_runtime.h>
#include <cuda_fp16.h>
#include <math.h>

#define Tt   64
#define Bb   128
#define Ee   1024
#define Hh   1024
#define Vv   10000
#define NBLK 12
#define GRID_R 128
#define VPAD 10112
#define PIPE 3

// ---------------- scratch (device globals) ----------------
__device__ __align__(16) float  g_XC[Tt*Bb*Hh];     // x @ wxc^T + b (f32, tf32 GEMM)
__device__ __align__(16) float  g_XH[Tt*Bb*Hh];
__device__ __align__(16) float  g_OUT[Tt*Bb*Hh];    // tf32-rounded pre-clip hidden (decoder A)
__device__ __align__(16) float  g_H[Bb*Hh];         // carried hidden f32
__device__ __align__(16) __half g_Hhp[Bb*Hh];       // fp16 twin (recurrence GEMM A)
__device__ __align__(16) float  g_Pc[2*Bb*Hh];      // split-K partials (kc=2), gate path
__device__ __align__(16) float  g_Ph[2*Bb*Hh];      // split-K partials, cand path
__device__ __align__(16) __half g_Wc[NBLK*Hh*Hh];   // fp16 [w_hc, edge_c x11]
__device__ __align__(16) __half g_Wh[NBLK*Hh*Hh];   // fp16 [w_hh, edge_h x11]
__device__ __align__(16) float  g_We[Vv*Ee];        // tf32 embedding
__device__ __align__(16) float  g_Wx[2*Hh*Ee];      // tf32 wxc, wxh
__device__ __align__(16) float  g_Wd[VPAD*Hh];      // tf32 + zero-padded dec_W
__device__ unsigned g_arr[GRID_R];

// ---------------- helpers ----------------
__device__ __forceinline__ unsigned f2tf32(float x){
  unsigned u; asm("cvt.rna.tf32.f32 %0, %1;" : "=r"(u) : "f"(x)); return u;
}
__device__ __forceinline__ float rndtf(float x){ return __uint_as_float(f2tf32(x)); }

__device__ __forceinline__ uint2 pack4h(float4 v){
  __half2 a = __floats2half2_rn(v.x, v.y);
  __half2 b = __floats2half2_rn(v.z, v.w);
  uint2 u;
  u.x = *(unsigned*)&a;
  u.y = *(unsigned*)&b;
  return u;
}

__device__ __forceinline__ void mma_tf32(float* c, const unsigned* a, const unsigned* b){
  asm volatile(
    "mma.sync.aligned.m16n8k8.row.col.f32.tf32.tf32.f32 "
    "{%0,%1,%2,%3}, {%4,%5,%6,%7}, {%8,%9}, {%0,%1,%2,%3};\n"
    : "+f"(c[0]), "+f"(c[1]), "+f"(c[2]), "+f"(c[3])
    : "r"(a[0]), "r"(a[1]), "r"(a[2]), "r"(a[3]), "r"(b[0]), "r"(b[1]));
}

__device__ __forceinline__ void mma_fp16(float* c, const unsigned* a, const unsigned* b){
  asm volatile(
    "mma.sync.aligned.m16n8k16.row.col.f32.f16.f16.f32 "
    "{%0,%1,%2,%3}, {%4,%5,%6,%7}, {%8,%9}, {%0,%1,%2,%3};\n"
    : "+f"(c[0]), "+f"(c[1]), "+f"(c[2]), "+f"(c[3])
    : "r"(a[0]), "r"(a[1]), "r"(a[2]), "r"(a[3]), "r"(b[0]), "r"(b[1]));
}

__device__ __forceinline__ void cpa16(void* smemp, const void* gmem){
  unsigned s = (unsigned)__cvta_generic_to_shared(smemp);
  asm volatile("cp.async.cg.shared.global [%0], [%1], 16;\n" :: "r"(s), "l"(gmem));
}
__device__ __forceinline__ void cpa_commit(){ asm volatile("cp.async.commit_group;\n"); }
template<int N> __device__ __forceinline__ void cpa_wait(){
  asm volatile("cp.async.wait_group %0;\n" :: "n"(N));
}

__device__ __forceinline__ float sigm(float x){ return 1.f/(1.f + expf(-x)); }

// symmetric grid barrier: every CTA publishes a flag; all CTAs poll all flags.
__device__ __forceinline__ void gsync(unsigned &ep){
  ep++;
  __syncthreads();
  if (threadIdx.x == 0){
    __threadfence();
    *(volatile unsigned*)&g_arr[blockIdx.x] = ep;
  }
  if (threadIdx.x < GRID_R){
    while (*(volatile unsigned*)&g_arr[threadIdx.x] < ep) { }
  }
  __syncthreads();
  __threadfence();
}

// tf32 warp tile 64x32 (mi4 x ni4), k-block 32 floats, smem row stride 36 u32
__device__ __forceinline__ void compute_64x32(const float* Af, const float* Bf,
      float acc[4][4][4], int wm, int wn, int g, int tg){
  const unsigned* As = (const unsigned*)Af;
  const unsigned* Bs = (const unsigned*)Bf;
#pragma unroll
  for (int ks = 0; ks < 32; ks += 8){
    unsigned a[4][4], b[4][2];
#pragma unroll
    for (int mi = 0; mi < 4; mi++){
      int r = wm + mi*16 + g;
      a[mi][0] = As[r*36 + ks+tg];
      a[mi][1] = As[(r+8)*36 + ks+tg];
      a[mi][2] = As[r*36 + ks+tg+4];
      a[mi][3] = As[(r+8)*36 + ks+tg+4];
    }
#pragma unroll
    for (int ni = 0; ni < 4; ni++){
      int rr = wn + ni*8 + g;
      b[ni][0] = Bs[rr*36 + ks+tg];
      b[ni][1] = Bs[rr*36 + ks+tg+4];
    }
#pragma unroll
    for (int mi = 0; mi < 4; mi++)
#pragma unroll
      for (int ni = 0; ni < 4; ni++)
        mma_tf32(acc[mi][ni], a[mi], b[ni]);
  }
}

// fp16 warp tile 64x8 (mi4 x ni1), k-block 64 halves, smem row stride 72 halves (36 u32)
__device__ __forceinline__ void compute_64x8h(const __half* Ah, const __half* Bh,
      float acc[4][4], int wm, int wn, int g, int tg){
  const unsigned* As = (const unsigned*)Ah;
  const unsigned* Bs = (const unsigned*)Bh;
#pragma unroll
  for (int ks = 0; ks < 64; ks += 16){
    int ko = ks/2 + tg;
    unsigned a[4][4], b[2];
#pragma unroll
    for (int mi = 0; mi < 4; mi++){
      int r = wm + mi*16 + g;
      a[mi][0] = As[r*36 + ko];
      a[mi][1] = As[(r+8)*36 + ko];
      a[mi][2] = As[r*36 + ko + 4];
      a[mi][3] = As[(r+8)*36 + ko + 4];
    }
    {
      int rr = wn + g;
      b[0] = Bs[rr*36 + ko];
      b[1] = Bs[rr*36 + ko + 4];
    }
#pragma unroll
    for (int mi = 0; mi < 4; mi++)
      mma_fp16(acc[mi], a[mi], b);
  }
}

// ---------------- prep: wc/wh -> fp16, we/wx/wd -> tf32 ----------------
#define S_WC  3145728L
#define S_WH  3145728L
#define S_WE  2560000L
#define S_WX   524288L
#define S_WD  2588672L
__global__ void __launch_bounds__(256) prep_all(
    const float* __restrict__ w_hc, const float* __restrict__ edge_c,
    const float* __restrict__ w_hh, const float* __restrict__ edge_h,
    const float* __restrict__ embW, const float* __restrict__ wxcW,
    const float* __restrict__ wxhW, const float* __restrict__ decW)
{
  long i = (long)blockIdx.x*256 + threadIdx.x;
  const long F4 = (long)Hh*Hh/4;
  if (i < S_WC){
    float4 v = (i < F4) ? ((const float4*)w_hc)[i] : ((const float4*)edge_c)[i-F4];
    ((uint2*)g_Wc)[i] = pack4h(v);
    return;
  }
  if ((i -= S_WC) < S_WH){
    float4 v = (i < F4) ? ((const float4*)w_hh)[i] : ((const float4*)edge_h)[i-F4];
    ((uint2*)g_Wh)[i] = pack4h(v);
    return;
  }
  float4 v; float4* dst;
  if ((i -= S_WH) < S_WE){
    v = ((const float4*)embW)[i];
    dst = ((float4*)g_We) + i;
  } else if ((i -= S_WE) < S_WX){
    const long G4 = (long)Hh*Ee/4;
    v = (i < G4) ? ((const float4*)wxcW)[i] : ((const float4*)wxhW)[i-G4];
    dst = ((float4*)g_Wx) + i;
  } else if ((i -= S_WX) < S_WD){
    long row = (i*4) >> 10;
    v = (row < Vv) ? ((const float4*)decW)[i] : make_float4(0.f,0.f,0.f,0.f);
    dst = ((float4*)g_Wd) + i;
  } else return;
  float4 r; r.x=rndtf(v.x); r.y=rndtf(v.y); r.z=rndtf(v.z); r.w=rndtf(v.w);
  *dst = r;
}

// ---------------- phase 1: input projections (tf32) ----------------
__global__ void __launch_bounds__(256) xproj_kernel(
    const int* __restrict__ tokens,
    const float* __restrict__ wxcB, const float* __restrict__ wxhB)
{
  extern __shared__ unsigned char smraw[];
  float* Ash = (float*)smraw;               // PIPE * 128*36 floats
  float* Bsh = (float*)smraw + PIPE*4608;   // PIPE * 128*36 floats
  __shared__ int toks[128];
  const int tid = threadIdx.x;
  const int n0 = blockIdx.x * 128;
  const int m0 = blockIdx.y * 128;
  const int mat = blockIdx.z;
  const float* W    = g_Wx + (size_t)mat*Hh*Ee;
  const float* bias = mat ? wxhB : wxcB;
  float* Cout = mat ? g_XH : g_XC;
  if (tid < 128) toks[tid] = tokens[m0 + tid];
  __syncthreads();
  const int lane = tid & 31, warp = tid >> 5;
  const int wm = (warp & 1) * 64, wn = (warp >> 1) * 32;
  const int g = lane >> 2, tg = lane & 3;

  float acc[4][4][4];
#pragma unroll
  for (int a=0;a<4;a++)
#pragma unroll
    for (int b=0;b<4;b++)
#pragma unroll
      for (int c=0;c<4;c++) acc[a][b][c]=0.f;

  auto load_tile = [&](int p, int kbi){
    int kb = kbi * 32;
#pragma unroll
    for (int i = 0; i < 4; i++){
      int idx = tid + i*256, row = idx>>3, c4 = (idx&7)*4;
      cpa16(&Ash[p*4608 + row*36 + c4], g_We + (size_t)toks[row]*Ee + kb + c4);
      cpa16(&Bsh[p*4608 + row*36 + c4], W + (size_t)(n0+row)*Ee + kb + c4);
    }
  };

#pragma unroll
  for (int p = 0; p < PIPE-1; p++){ load_tile(p, p); cpa_commit(); }
  for (int it = 0; it < 32; it++){
    cpa_wait<PIPE-2>();
    __syncthreads();
    int nx = it + PIPE - 1;
    if (nx < 32) load_tile(nx % PIPE, nx);
    cpa_commit();
    compute_64x32(Ash + (it%PIPE)*4608, Bsh + (it%PIPE)*4608, acc, wm, wn, g, tg);
  }

#pragma unroll
  for (int mi=0; mi<4; mi++){
    int r = m0 + wm + mi*16 + g;
#pragma unroll
    for (int ni=0; ni<4; ni++){
      int c = n0 + wn + ni*8 + 2*tg;
      float b0 = bias[c], b1 = bias[c+1];
      size_t o = (size_t)r*Hh + c;
      Cout[o]        = acc[mi][ni][0] + b0;
      Cout[o+1]      = acc[mi][ni][1] + b1;
      Cout[o+8*Hh]   = acc[mi][ni][2] + b0;
      Cout[o+8*Hh+1] = acc[mi][ni][3] + b1;
    }
  }
}

// ---------------- phase 2: persistent recurrence (fp16 mma) ----------------
// 128 CTAs: kc(2) x nt(32) x mat(2). CTA tile 128(M) x 32(N) x 512(K).
// Full-stage A preload (8 k-blocks of 64), B double-buffered full-stage tiles.
__global__ void __launch_bounds__(256) rnn_kernel(float* __restrict__ outp)
{
  extern __shared__ unsigned char smraw[];
  __half* Aw = (__half*)smraw;               // 8 * 128*72 halves   (147456 B)
  __half* Bw = (__half*)smraw + 8*9216;      // 2 * 8 * 32*72 halves (73728 B)
  __shared__ float red[9];
  const int tid = threadIdx.x;
  const int bid = blockIdx.x;
  const int lane = tid & 31, warp = tid >> 5;
  const int wm = (warp & 1) * 64, wn = (warp >> 1) * 8;
  const int g = lane >> 2, tg = lane & 3;
  const int kc  = bid & 1;
  const int nt  = (bid >> 1) & 31;
  const int mat = bid >> 6;
  const int n0 = nt * 32;
  const int k0 = kc * 512;
  const int f  = bid * 256 + tid;      // float4 index over 128x1024
  unsigned ep = 0;

  const __half* Wbase = mat ? g_Wh : g_Wc;

  // B tile for stage s: rows n0..n0+31, k k0..k0+511, as 8 chunks of [32][72] halves
  auto load_B = [&](int s, __half* dst){
    const __half* W = Wbase + (size_t)s*Hh*Hh;
#pragma unroll
    for (int i = 0; i < 8; i++){
      int idx = tid + i*256;
      int kb = idx >> 8;               // 8 chunks, 256 cpa16 each
      int j  = idx & 255;
      int row = j >> 3, c8 = (j & 7) * 8;
      cpa16(&dst[kb*2304 + row*72 + c8], W + (size_t)(n0+row)*Hh + k0 + kb*64 + c8);
    }
  };
  auto load_A = [&](int kb){
#pragma unroll
    for (int i = 0; i < 4; i++){
      int idx = tid + i*256, row = idx>>3, c8 = (idx&7)*8;
      cpa16(&Aw[kb*9216 + row*72 + c8], g_Hhp + (size_t)row*Hh + k0 + kb*64 + c8);
    }
  };

  // prologue: stage-0 weights (independent of h)
  load_B(0, Bw); cpa_commit();

  // h0 = 0
  {
    ((float4*)g_H)[f] = make_float4(0.f,0.f,0.f,0.f);
    uint2 z2; z2.x = 0u; z2.y = 0u;
    ((uint2*)g_Hhp)[f] = z2;
  }
  gsync(ep);

  for (int t = 0; t < Tt; t++){
    for (int s = 0; s < NBLK; s++){
      __half* Bcur = Bw + (s & 1) * 18432;
      __half* Bnxt = Bw + ((s + 1) & 1) * 18432;

      float acc[4][4];
#pragma unroll
      for (int a=0;a<4;a++)
#pragma unroll
        for (int c=0;c<4;c++) acc[a][c]=0.f;

      // issue the whole stage: A0..A7, then next-stage B (into the other buffer)
      load_A(0); cpa_commit();
      load_A(1); cpa_commit();
      load_A(2); cpa_commit();
      load_A(3); cpa_commit();
      load_A(4); cpa_commit();
      load_A(5); cpa_commit();
      load_A(6); cpa_commit();
      load_A(7); cpa_commit();
      {
        int sn = s + 1; if (sn == NBLK) sn = 0;
        load_B(sn, Bnxt); cpa_commit();
      }

      cpa_wait<8>(); __syncthreads();
      compute_64x8h(Aw + 0*9216, Bcur + 0*2304, acc, wm, wn, g, tg);
      cpa_wait<7>(); __syncthreads();
      compute_64x8h(Aw + 1*9216, Bcur + 1*2304, acc, wm, wn, g, tg);
      cpa_wait<6>(); __syncthreads();
      compute_64x8h(Aw + 2*9216, Bcur + 2*2304, acc, wm, wn, g, tg);
      cpa_wait<5>(); __syncthreads();
      compute_64x8h(Aw + 3*9216, Bcur + 3*2304, acc, wm, wn, g, tg);
      cpa_wait<4>(); __syncthreads();
      compute_64x8h(Aw + 4*9216, Bcur + 4*2304, acc, wm, wn, g, tg);
      cpa_wait<3>(); __syncthreads();
      compute_64x8h(Aw + 5*9216, Bcur + 5*2304, acc, wm, wn, g, tg);
      cpa_wait<2>(); __syncthreads();
      compute_64x8h(Aw + 6*9216, Bcur + 6*2304, acc, wm, wn, g, tg);
      cpa_wait<1>(); __syncthreads();
      compute_64x8h(Aw + 7*9216, Bcur + 7*2304, acc, wm, wn, g, tg);

      // write split-K partial (f32); kc in {0,1}
      float* Pd = (mat ? g_Ph : g_Pc) + ((size_t)kc << 17);
#pragma unroll
      for (int mi=0; mi<4; mi++){
        int r = wm + mi*16 + g;
        int c = n0 + wn + 2*tg;
        Pd[(size_t)r*Hh + c]       = acc[mi][0];
        Pd[(size_t)r*Hh + c+1]     = acc[mi][1];
        Pd[(size_t)(r+8)*Hh + c]   = acc[mi][2];
        Pd[(size_t)(r+8)*Hh + c+1] = acc[mi][3];
      }
      gsync(ep);

      // fused reduce + gate + activation + blend; thread f owns 4 floats of row bid
      {
        float4 sc = make_float4(0.f,0.f,0.f,0.f);
        float4 sh = make_float4(0.f,0.f,0.f,0.f);
#pragma unroll
        for (int k = 0; k < 2; k++){
          float4 a  = ((const float4*)(g_Pc + ((size_t)k<<17)))[f];
          sc.x += a.x; sc.y += a.y; sc.z += a.z; sc.w += a.w;
          float4 b2 = ((const float4*)(g_Ph + ((size_t)k<<17)))[f];
          sh.x += b2.x; sh.y += b2.y; sh.z += b2.z; sh.w += b2.w;
        }
        if (s == 0){
          float4 a  = ((const float4*)g_XC)[((size_t)t<<15) + f];
          sc.x += a.x; sc.y += a.y; sc.z += a.z; sc.w += a.w;
          float4 b2 = ((const float4*)g_XH)[((size_t)t<<15) + f];
          sh.x += b2.x; sh.y += b2.y; sh.z += b2.z; sh.w += b2.w;
        }
        float4 h = ((const float4*)g_H)[f];
        const bool use_tanh = (s == 0) || (s & 1);
        float gx = sigm(sc.x), gy = sigm(sc.y), gz = sigm(sc.z), gw = sigm(sc.w);
        float ax = use_tanh ? tanhf(sh.x) : fmaxf(sh.x, 0.f);
        float ay = use_tanh ? tanhf(sh.y) : fmaxf(sh.y, 0.f);
        float az = use_tanh ? tanhf(sh.z) : fmaxf(sh.z, 0.f);
        float aw = use_tanh ? tanhf(sh.w) : fmaxf(sh.w, 0.f);
        float4 hn;
        hn.x = gx*ax + (1.f-gx)*h.x;
        hn.y = gy*ay + (1.f-gy)*h.y;
        hn.z = gz*az + (1.f-gz)*h.z;
        hn.w = gw*aw + (1.f-gw)*h.w;

        if (s == NBLK-1){
          // pre-clip output for decoder: tf32-rounded f32
          float4 pre;
          pre.x=rndtf(hn.x); pre.y=rndtf(hn.y); pre.z=rndtf(hn.z); pre.w=rndtf(hn.w);
          ((float4*)g_OUT)[((size_t)t<<15) + f] = pre;
          // fused per-row norm clip: this CTA owns exactly row bid
          float ss = hn.x*hn.x + hn.y*hn.y + hn.z*hn.z + hn.w*hn.w;
#pragma unroll
          for (int off = 16; off > 0; off >>= 1) ss += __shfl_xor_sync(0xffffffffu, ss, off);
          if (lane == 0) red[warp] = ss;
          __syncthreads();
          if (tid == 0){
            float tot = 0.f;
#pragma unroll
            for (int w2 = 0; w2 < 8; w2++) tot += red[w2];
            float nrm = sqrtf(tot);
            red[8] = (nrm > 25.f) ? (25.f / nrm) : 1.f;
          }
          __syncthreads();
          float scl = red[8];
          hn.x *= scl; hn.y *= scl; hn.z *= scl; hn.w *= scl;
        }
        ((float4*)g_H)[f] = hn;
        ((uint2*)g_Hhp)[f] = pack4h(hn);
      }
      gsync(ep);
    }
  }

  // hT (clipped final hidden) appended after decoded
  {
    float4 h = ((const float4*)g_H)[f];
    float* o = outp + (size_t)Tt*Bb*Vv + (size_t)f*4;
    o[0]=h.x; o[1]=h.y; o[2]=h.z; o[3]=h.w;
  }
}

// ---------------- phase 3: decoder GEMM (tf32) ----------------
__global__ void __launch_bounds__(256) dec_kernel(
  const float* __restrict__ decB, float* __restrict__ outp)
{
  extern __shared__ unsigned char smraw[];
  float* Ash = (float*)smraw;
  float* Bsh = (float*)smraw + PIPE*4608;
  const int tid = threadIdx.x;
  const int n0 = blockIdx.x * 128;
  const int m0 = blockIdx.y * 128;
  const int lane = tid & 31, warp = tid >> 5;
  const int wm = (warp & 1) * 64, wn = (warp >> 1) * 32;
  const int g = lane >> 2, tg = lane & 3;
  float acc[4][4][4];
#pragma unroll
  for (int a=0;a<4;a++)
#pragma unroll
    for (int b=0;b<4;b++)
#pragma unroll
      for (int c=0;c<4;c++) acc[a][b][c]=0.f;

  auto load_tile = [&](int p, int kbi){
    int kb = kbi * 32;
#pragma unroll
    for (int i = 0; i < 4; i++){
      int idx = tid + i*256, row = idx>>3, c4 = (idx&7)*4;
      cpa16(&Ash[p*4608 + row*36 + c4], g_OUT + (size_t)(m0+row)*Hh + kb + c4);
      cpa16(&Bsh[p*4608 + row*36 + c4], g_Wd + (size_t)(n0+row)*Hh + kb + c4);
    }
  };

#pragma unroll
  for (int p = 0; p < PIPE-1; p++){ load_tile(p, p); cpa_commit(); }
  for (int it = 0; it < 32; it++){
    cpa_wait<PIPE-2>();
    __syncthreads();
    int nx = it + PIPE - 1;
    if (nx < 32) load_tile(nx % PIPE, nx);
    cpa_commit();
    compute_64x32(Ash + (it%PIPE)*4608, Bsh + (it%PIPE)*4608, acc, wm, wn, g, tg);
  }

#pragma unroll
  for (int mi=0;mi<4;mi++){
    int r = m0 + wm + mi*16 + g;
#pragma unroll
    for (int ni=0;ni<4;ni++){
      int c = n0 + wn + ni*8 + 2*tg;
      if (c < Vv){
        float b0 = decB[c], b1 = decB[c+1];
        size_t o  = (size_t)r*Vv + c;
        size_t o2 = o + (size_t)8*Vv;
        outp[o]    = acc[mi][ni][0] + b0;
        outp[o+1]  = acc[mi][ni][1] + b1;
        outp[o2]   = acc[mi][ni][2] + b0;
        outp[o2+1] = acc[mi][ni][3] + b1;
      }
    }
  }
}

// ---------------- launch ----------------
extern "C" void kernel_launch(void* const* d_in, const int* in_sizes, int n_in,
                              void* d_out, int out_size){
  const int*   tokens = (const int*)  d_in[0];
  const float* embW   = (const float*)d_in[1];
  const float* wxcW   = (const float*)d_in[2];
  const float* wxcB   = (const float*)d_in[3];
  const float* wxhW   = (const float*)d_in[4];
  const float* wxhB   = (const float*)d_in[5];
  const float* w_hc   = (const float*)d_in[6];
  const float* w_hh   = (const float*)d_in[7];
  const float* edge_h = (const float*)d_in[8];
  const float* edge_c = (const float*)d_in[9];
  const float* decW   = (const float*)d_in[10];
  const float* decB   = (const float*)d_in[11];
  float* outp = (float*)d_out;
  (void)in_sizes; (void)n_in; (void)out_size;

  const int RNN_SMEM  = (8*9216 + 2*8*2304) * 2;   // 221184 B (halves)
  const int GEMM_SMEM = PIPE * 2 * 4608 * 4;       // 110592 B (floats, tf32)
  cudaFuncSetAttribute(xproj_kernel, cudaFuncAttributeMaxDynamicSharedMemorySize, GEMM_SMEM);
  cudaFuncSetAttribute(rnn_kernel,   cudaFuncAttributeMaxDynamicSharedMemorySize, RNN_SMEM);
  cudaFuncSetAttribute(dec_kernel,   cudaFuncAttributeMaxDynamicSharedMemorySize, GEMM_SMEM);

  // reset barrier flags
  void *pArr = nullptr;
  cudaGetSymbolAddress(&pArr, g_arr);
  cudaMemsetAsync(pArr, 0, sizeof(unsigned)*GRID_R);

  const long PREP_TOTAL = S_WC + S_WH + S_WE + S_WX + S_WD;
  prep_all<<<(unsigned)((PREP_TOTAL + 255) / 256), 256>>>(
      w_hc, edge_c, w_hh, edge_h, embW, wxcW, wxhW, decW);

  xproj_kernel<<<dim3(8, 64, 2), 256, GEMM_SMEM>>>(tokens, wxcB, wxhB);
  rnn_kernel<<<GRID_R, 256, RNN_SMEM>>>(outp);
  dec_kernel<<<dim3(VPAD/128, 64), 256, GEMM_SMEM>>>(decB, outp);
}

// round 11
// speedup vs baseline: 1.5597x; 1.5597x over previous
#include <cuda_runtime.h>
#include <cuda_fp16.h>
#include <math.h>

#define Tt   64
#define Bb   128
#define Ee   1024
#define Hh   1024
#define Vv   10000
#define NBLK 12
#define GRID_R 128
#define VPAD 10112
#define PIPE 3

// ---------------- scratch (device globals) ----------------
__device__ __align__(16) float  g_XC[Tt*Bb*Hh];     // x @ wxc^T + b (f32, tf32 GEMM)
__device__ __align__(16) float  g_XH[Tt*Bb*Hh];
__device__ __align__(16) float  g_OUT[Tt*Bb*Hh];    // tf32-rounded pre-clip hidden (decoder A)
__device__ __align__(16) float  g_Hf[2*Bb*Hh];      // carried hidden f32, stage-parity double buffer
__device__ __align__(16) __half g_Hh2[2*Bb*Hh];     // fp16 twin (recurrence GEMM A), double buffer
__device__ __align__(16) __half g_Wc[NBLK*Hh*Hh];   // fp16 [w_hc, edge_c x11]  (gate)
__device__ __align__(16) __half g_Wh[NBLK*Hh*Hh];   // fp16 [w_hh, edge_h x11]  (candidate)
__device__ __align__(16) float  g_We[Vv*Ee];        // tf32 embedding
__device__ __align__(16) float  g_Wx[2*Hh*Ee];      // tf32 wxc, wxh
__device__ __align__(16) float  g_Wd[VPAD*Hh];      // tf32 + zero-padded dec_W
__device__ unsigned g_arr[GRID_R];
__device__ unsigned g_rel;

// ---------------- helpers ----------------
__device__ __forceinline__ unsigned f2tf32(float x){
  unsigned u; asm("cvt.rna.tf32.f32 %0, %1;" : "=r"(u) : "f"(x)); return u;
}
__device__ __forceinline__ float rndtf(float x){ return __uint_as_float(f2tf32(x)); }

__device__ __forceinline__ uint2 pack4h(float4 v){
  __half2 a = __floats2half2_rn(v.x, v.y);
  __half2 b = __floats2half2_rn(v.z, v.w);
  uint2 u;
  u.x = *(unsigned*)&a;
  u.y = *(unsigned*)&b;
  return u;
}

__device__ __forceinline__ void mma_tf32(float* c, const unsigned* a, const unsigned* b){
  asm volatile(
    "mma.sync.aligned.m16n8k8.row.col.f32.tf32.tf32.f32 "
    "{%0,%1,%2,%3}, {%4,%5,%6,%7}, {%8,%9}, {%0,%1,%2,%3};\n"
    : "+f"(c[0]), "+f"(c[1]), "+f"(c[2]), "+f"(c[3])
    : "r"(a[0]), "r"(a[1]), "r"(a[2]), "r"(a[3]), "r"(b[0]), "r"(b[1]));
}

__device__ __forceinline__ void mma_fp16(float* c, const unsigned* a, const unsigned* b){
  asm volatile(
    "mma.sync.aligned.m16n8k16.row.col.f32.f16.f16.f32 "
    "{%0,%1,%2,%3}, {%4,%5,%6,%7}, {%8,%9}, {%0,%1,%2,%3};\n"
    : "+f"(c[0]), "+f"(c[1]), "+f"(c[2]), "+f"(c[3])
    : "r"(a[0]), "r"(a[1]), "r"(a[2]), "r"(a[3]), "r"(b[0]), "r"(b[1]));
}

__device__ __forceinline__ void cpa16(void* smemp, const void* gmem){
  unsigned s = (unsigned)__cvta_generic_to_shared(smemp);
  asm volatile("cp.async.cg.shared.global [%0], [%1], 16;\n" :: "r"(s), "l"(gmem));
}
__device__ __forceinline__ void cpa_commit(){ asm volatile("cp.async.commit_group;\n"); }
template<int N> __device__ __forceinline__ void cpa_wait(){
  asm volatile("cp.async.wait_group %0;\n" :: "n"(N));
}

__device__ __forceinline__ float sigm(float x){ return 1.f/(1.f + expf(-x)); }

// grid barrier (r7 two-hop): per-CTA flag words, CTA0 scans, single release word.
__device__ __forceinline__ void gsync(unsigned &ep){
  ep++;
  __syncthreads();
  if (blockIdx.x == 0){
    if (threadIdx.x > 0 && threadIdx.x < GRID_R){
      while (*(volatile unsigned*)&g_arr[threadIdx.x] < ep) { }
    }
    __syncthreads();
    if (threadIdx.x == 0){ __threadfence(); *(volatile unsigned*)&g_rel = ep; }
  } else {
    if (threadIdx.x == 0){
      __threadfence();
      *(volatile unsigned*)&g_arr[blockIdx.x] = ep;
      while (*(volatile unsigned*)&g_rel < ep) { }
    }
  }
  __syncthreads();
  __threadfence();
}

// tf32 warp tile 64x32 (mi4 x ni4), k-block 32 floats, smem row stride 36 u32
__device__ __forceinline__ void compute_64x32(const float* Af, const float* Bf,
      float acc[4][4][4], int wm, int wn, int g, int tg){
  const unsigned* As = (const unsigned*)Af;
  const unsigned* Bs = (const unsigned*)Bf;
#pragma unroll
  for (int ks = 0; ks < 32; ks += 8){
    unsigned a[4][4], b[4][2];
#pragma unroll
    for (int mi = 0; mi < 4; mi++){
      int r = wm + mi*16 + g;
      a[mi][0] = As[r*36 + ks+tg];
      a[mi][1] = As[(r+8)*36 + ks+tg];
      a[mi][2] = As[r*36 + ks+tg+4];
      a[mi][3] = As[(r+8)*36 + ks+tg+4];
    }
#pragma unroll
    for (int ni = 0; ni < 4; ni++){
      int rr = wn + ni*8 + g;
      b[ni][0] = Bs[rr*36 + ks+tg];
      b[ni][1] = Bs[rr*36 + ks+tg+4];
    }
#pragma unroll
    for (int mi = 0; mi < 4; mi++)
#pragma unroll
      for (int ni = 0; ni < 4; ni++)
        mma_tf32(acc[mi][ni], a[mi], b[ni]);
  }
}

// fp16: one 64-k block, warp tile 16(M)x8(N), BOTH mats share the A fragments.
// A block: [128][72] halves; B blocks: [8][72] halves each.
__device__ __forceinline__ void compute_blk(const __half* Ab, const __half* Bc, const __half* Bh,
      float accc[4], float acch[4], int wm, int g, int tg){
  const unsigned* As  = (const unsigned*)Ab;
  const unsigned* Bcs = (const unsigned*)Bc;
  const unsigned* Bhs = (const unsigned*)Bh;
#pragma unroll
  for (int ks = 0; ks < 4; ks++){
    int ko = ks*8 + tg;
    unsigned a[4];
    a[0] = As[(wm+g)*36 + ko];
    a[1] = As[(wm+g+8)*36 + ko];
    a[2] = As[(wm+g)*36 + ko + 4];
    a[3] = As[(wm+g+8)*36 + ko + 4];
    unsigned bc[2] = { Bcs[g*36 + ko], Bcs[g*36 + ko + 4] };
    unsigned bh[2] = { Bhs[g*36 + ko], Bhs[g*36 + ko + 4] };
    mma_fp16(accc, a, bc);
    mma_fp16(acch, a, bh);
  }
}

// ---------------- prep: wc/wh -> fp16, we/wx/wd -> tf32 ----------------
#define S_WC  3145728L
#define S_WH  3145728L
#define S_WE  2560000L
#define S_WX   524288L
#define S_WD  2588672L
__global__ void __launch_bounds__(256) prep_all(
    const float* __restrict__ w_hc, const float* __restrict__ edge_c,
    const float* __restrict__ w_hh, const float* __restrict__ edge_h,
    const float* __restrict__ embW, const float* __restrict__ wxcW,
    const float* __restrict__ wxhW, const float* __restrict__ decW)
{
  long i = (long)blockIdx.x*256 + threadIdx.x;
  const long F4 = (long)Hh*Hh/4;
  if (i < S_WC){
    float4 v = (i < F4) ? ((const float4*)w_hc)[i] : ((const float4*)edge_c)[i-F4];
    ((uint2*)g_Wc)[i] = pack4h(v);
    return;
  }
  if ((i -= S_WC) < S_WH){
    float4 v = (i < F4) ? ((const float4*)w_hh)[i] : ((const float4*)edge_h)[i-F4];
    ((uint2*)g_Wh)[i] = pack4h(v);
    return;
  }
  float4 v; float4* dst;
  if ((i -= S_WH) < S_WE){
    v = ((const float4*)embW)[i];
    dst = ((float4*)g_We) + i;
  } else if ((i -= S_WE) < S_WX){
    const long G4 = (long)Hh*Ee/4;
    v = (i < G4) ? ((const float4*)wxcW)[i] : ((const float4*)wxhW)[i-G4];
    dst = ((float4*)g_Wx) + i;
  } else if ((i -= S_WX) < S_WD){
    long row = (i*4) >> 10;
    v = (row < Vv) ? ((const float4*)decW)[i] : make_float4(0.f,0.f,0.f,0.f);
    dst = ((float4*)g_Wd) + i;
  } else return;
  float4 r; r.x=rndtf(v.x); r.y=rndtf(v.y); r.z=rndtf(v.z); r.w=rndtf(v.w);
  *dst = r;
}

// ---------------- phase 1: input projections (tf32) ----------------
__global__ void __launch_bounds__(256) xproj_kernel(
    const int* __restrict__ tokens,
    const float* __restrict__ wxcB, const float* __restrict__ wxhB)
{
  extern __shared__ unsigned char smraw[];
  float* Ash = (float*)smraw;               // PIPE * 128*36 floats
  float* Bsh = (float*)smraw + PIPE*4608;   // PIPE * 128*36 floats
  __shared__ int toks[128];
  const int tid = threadIdx.x;
  const int n0 = blockIdx.x * 128;
  const int m0 = blockIdx.y * 128;
  const int mat = blockIdx.z;
  const float* W    = g_Wx + (size_t)mat*Hh*Ee;
  const float* bias = mat ? wxhB : wxcB;
  float* Cout = mat ? g_XH : g_XC;
  if (tid < 128) toks[tid] = tokens[m0 + tid];
  __syncthreads();
  const int lane = tid & 31, warp = tid >> 5;
  const int wm = (warp & 1) * 64, wn = (warp >> 1) * 32;
  const int g = lane >> 2, tg = lane & 3;

  float acc[4][4][4];
#pragma unroll
  for (int a=0;a<4;a++)
#pragma unroll
    for (int b=0;b<4;b++)
#pragma unroll
      for (int c=0;c<4;c++) acc[a][b][c]=0.f;

  auto load_tile = [&](int p, int kbi){
    int kb = kbi * 32;
#pragma unroll
    for (int i = 0; i < 4; i++){
      int idx = tid + i*256, row = idx>>3, c4 = (idx&7)*4;
      cpa16(&Ash[p*4608 + row*36 + c4], g_We + (size_t)toks[row]*Ee + kb + c4);
      cpa16(&Bsh[p*4608 + row*36 + c4], W + (size_t)(n0+row)*Ee + kb + c4);
    }
  };

#pragma unroll
  for (int p = 0; p < PIPE-1; p++){ load_tile(p, p); cpa_commit(); }
  for (int it = 0; it < 32; it++){
    cpa_wait<PIPE-2>();
    __syncthreads();
    int nx = it + PIPE - 1;
    if (nx < 32) load_tile(nx % PIPE, nx);
    cpa_commit();
    compute_64x32(Ash + (it%PIPE)*4608, Bsh + (it%PIPE)*4608, acc, wm, wn, g, tg);
  }

#pragma unroll
  for (int mi=0; mi<4; mi++){
    int r = m0 + wm + mi*16 + g;
#pragma unroll
    for (int ni=0; ni<4; ni++){
      int c = n0 + wn + ni*8 + 2*tg;
      float b0 = bias[c], b1 = bias[c+1];
      size_t o = (size_t)r*Hh + c;
      Cout[o]        = acc[mi][ni][0] + b0;
      Cout[o+1]      = acc[mi][ni][1] + b1;
      Cout[o+8*Hh]   = acc[mi][ni][2] + b0;
      Cout[o+8*Hh+1] = acc[mi][ni][3] + b1;
    }
  }
}

// ---------------- phase 2: persistent recurrence (fp16 mma, fused gate) ----------------
// 128 CTAs, CTA bid owns N columns [bid*8, bid*8+8) for BOTH mats, full K=1024.
// A (hidden, fp16) streamed in 4 chunks of 128x256, ping-pong smem buffers.
// B (both mats, 8x1024 each) resident; next stage's B prefetched during mainloop.
// Epilogue computes gate+blend in registers; ONE grid barrier per stage.
__global__ void __launch_bounds__(256) rnn_kernel(float* __restrict__ outp)
{
  extern __shared__ unsigned char smraw[];
  __half* Aw = (__half*)smraw;               // 2 x 36864 halves (2 chunks of 4 blocks [128][72])
  __half* Bw = (__half*)smraw + 73728;       // 2 x 18432 halves (2 stages x 2 mats x 16 blocks [8][72])
  __shared__ float red[9];
  const int tid = threadIdx.x;
  const int bid = blockIdx.x;
  const int lane = tid & 31, warp = tid >> 5;
  const int wm = warp * 16;
  const int g = lane >> 2, tg = lane & 3;
  const int n0 = bid * 8;
  const int r0 = wm + g, r1 = wm + g + 8;
  const int c0 = n0 + 2*tg;
  unsigned ep = 0;

  auto load_A = [&](int par, int kb, int p){   // chunk kb (0..3) of h buffer par
    const __half* src = g_Hh2 + (size_t)par*Bb*Hh;
#pragma unroll
    for (int i = 0; i < 16; i++){
      int idx = tid + i*256;                   // 4096 cpa16 per chunk
      int row = idx >> 5;
      int kh  = (idx & 31) * 8;                // half offset within 256-k chunk
      int blk = kh >> 6, kk = kh & 63;
      cpa16(&Aw[p*36864 + blk*9216 + row*72 + kk],
            src + (size_t)row*Hh + kb*256 + kh);
    }
  };
  auto load_B = [&](int s, int q){
#pragma unroll
    for (int i = 0; i < 8; i++){
      int idx = tid + i*256;                   // 2048 cpa16 per stage (both mats)
      int m2 = idx >> 10;
      int j  = idx & 1023;
      int blk = j >> 6;                        // 0..15
      int jj = j & 63;
      int row = jj >> 3, c8 = (jj & 7) * 8;
      const __half* W = (m2 ? g_Wh : g_Wc) + (size_t)s*Hh*Hh;
      cpa16(&Bw[q*18432 + m2*9216 + blk*576 + row*72 + c8],
            W + (size_t)(n0+row)*Hh + blk*64 + c8);
    }
  };

  // prologue: stage-0 weights; zero h buffer 0 (f32 + fp16)
  load_B(0, 0); cpa_commit();
  {
    int i4 = bid*256 + tid;                    // 32768 float4 = buffer 0 of g_Hf
    ((float4*)g_Hf)[i4] = make_float4(0.f,0.f,0.f,0.f);
    if (i4 < Bb*Hh/8){                         // 16384 uint2 = buffer 0 of g_Hh2
      uint2 z; z.x = 0u; z.y = 0u;
      ((uint2*)g_Hh2)[i4] = z;
    }
  }
  gsync(ep);

  for (int t = 0; t < Tt; t++){
    for (int s = 0; s < NBLK; s++){
      const int par = s & 1;                   // h & B buffers for this stage
      const __half* Bc = Bw + par*18432;       // gate weights (16 blocks)
      const __half* Bh = Bw + par*18432 + 9216;

      float accc[4] = {0.f,0.f,0.f,0.f};
      float acch[4] = {0.f,0.f,0.f,0.f};

      // issue: A0, A1, next-stage B
      load_A(par, 0, 0); cpa_commit();
      load_A(par, 1, 1); cpa_commit();
      {
        int sn = s + 1; if (sn == NBLK) sn = 0;
        load_B(sn, par ^ 1); cpa_commit();
      }

      // iter 0: chunk 0 (blocks 0..3)
      cpa_wait<2>(); __syncthreads();
#pragma unroll
      for (int b = 0; b < 4; b++)
        compute_blk(Aw + 0*36864 + b*9216, Bc + (0*4+b)*576, Bh + (0*4+b)*576, accc, acch, wm, g, tg);
      __syncthreads();
      load_A(par, 2, 0); cpa_commit();

      // iter 1: chunk 1 (blocks 4..7)
      cpa_wait<2>(); __syncthreads();
#pragma unroll
      for (int b = 0; b < 4; b++)
        compute_blk(Aw + 1*36864 + b*9216, Bc + (1*4+b)*576, Bh + (1*4+b)*576, accc, acch, wm, g, tg);
      __syncthreads();
      load_A(par, 3, 1); cpa_commit();

      // iter 2: chunk 2 (blocks 8..11)
      cpa_wait<1>(); __syncthreads();
#pragma unroll
      for (int b = 0; b < 4; b++)
        compute_blk(Aw + 0*36864 + b*9216, Bc + (2*4+b)*576, Bh + (2*4+b)*576, accc, acch, wm, g, tg);

      // iter 3: chunk 3 (blocks 12..15); wait<0> also guarantees next-stage B landed
      cpa_wait<0>(); __syncthreads();
#pragma unroll
      for (int b = 0; b < 4; b++)
        compute_blk(Aw + 1*36864 + b*9216, Bc + (3*4+b)*576, Bh + (3*4+b)*576, accc, acch, wm, g, tg);

      // fused epilogue: gate + activation + blend for this thread's 4 elements
      {
        const int np = par ^ 1;
        const float* Hprev = g_Hf + (size_t)par*Bb*Hh;
        float*       Hnext = g_Hf + (size_t)np *Bb*Hh;
        __half*      Hh16  = g_Hh2 + (size_t)np*Bb*Hh;

        float sc0=accc[0], sc1=accc[1], sc2=accc[2], sc3=accc[3];
        float sh0=acch[0], sh1=acch[1], sh2=acch[2], sh3=acch[3];
        if (s == 0){
          const float* XCb = g_XC + ((size_t)t<<17);
          const float* XHb = g_XH + ((size_t)t<<17);
          float2 a0 = *(const float2*)(XCb + (size_t)r0*Hh + c0);
          float2 a1 = *(const float2*)(XCb + (size_t)r1*Hh + c0);
          float2 b0 = *(const float2*)(XHb + (size_t)r0*Hh + c0);
          float2 b1 = *(const float2*)(XHb + (size_t)r1*Hh + c0);
          sc0 += a0.x; sc1 += a0.y; sc2 += a1.x; sc3 += a1.y;
          sh0 += b0.x; sh1 += b0.y; sh2 += b1.x; sh3 += b1.y;
        }
        float2 h0 = *(const float2*)(Hprev + (size_t)r0*Hh + c0);
        float2 h1 = *(const float2*)(Hprev + (size_t)r1*Hh + c0);
        const bool use_tanh = (s == 0) || (s & 1);
        float g0 = sigm(sc0), g1 = sigm(sc1), g2 = sigm(sc2), g3 = sigm(sc3);
        float a0 = use_tanh ? tanhf(sh0) : fmaxf(sh0, 0.f);
        float a1 = use_tanh ? tanhf(sh1) : fmaxf(sh1, 0.f);
        float a2 = use_tanh ? tanhf(sh2) : fmaxf(sh2, 0.f);
        float a3 = use_tanh ? tanhf(sh3) : fmaxf(sh3, 0.f);
        float n0v = g0*a0 + (1.f-g0)*h0.x;
        float n1v = g1*a1 + (1.f-g1)*h0.y;
        float n2v = g2*a2 + (1.f-g2)*h1.x;
        float n3v = g3*a3 + (1.f-g3)*h1.y;
        *(float2*)(Hnext + (size_t)r0*Hh + c0) = make_float2(n0v, n1v);
        *(float2*)(Hnext + (size_t)r1*Hh + c0) = make_float2(n2v, n3v);
        __half2 p0 = __floats2half2_rn(n0v, n1v);
        __half2 p1 = __floats2half2_rn(n2v, n3v);
        *(unsigned*)(Hh16 + (size_t)r0*Hh + c0) = *(unsigned*)&p0;
        *(unsigned*)(Hh16 + (size_t)r1*Hh + c0) = *(unsigned*)&p1;
        if (s == NBLK-1){
          float* Ob = g_OUT + ((size_t)t<<17);
          *(float2*)(Ob + (size_t)r0*Hh + c0) = make_float2(rndtf(n0v), rndtf(n1v));
          *(float2*)(Ob + (size_t)r1*Hh + c0) = make_float2(rndtf(n2v), rndtf(n3v));
        }
      }
      gsync(ep);
    }

    // per-row norm clip on buffer 0 (h written at s=11 lands in buf 0); CTA bid owns row bid
    {
      float*  hr = g_Hf  + (size_t)bid * Hh;
      __half* hh = g_Hh2 + (size_t)bid * Hh;
      float ss = 0.f;
      for (int i = tid; i < Hh; i += 256){ float v = hr[i]; ss += v*v; }
#pragma unroll
      for (int off = 16; off > 0; off >>= 1) ss += __shfl_xor_sync(0xffffffffu, ss, off);
      if (lane == 0) red[warp] = ss;
      __syncthreads();
      if (tid == 0){
        float tot = 0.f;
#pragma unroll
        for (int w2 = 0; w2 < 8; w2++) tot += red[w2];
        float nrm = sqrtf(tot);
        red[8] = (nrm > 25.f) ? (25.f / nrm) : 1.f;
      }
      __syncthreads();
      float scl = red[8];
      if (scl != 1.f){
        for (int i = tid; i < Hh; i += 256){
          float v = hr[i] * scl;
          hr[i] = v;
          hh[i] = __float2half_rn(v);
        }
      }
    }
    gsync(ep);
  }

  // hT (clipped final hidden, buffer 0) appended after decoded
  {
    const float* hr = g_Hf + (size_t)bid * Hh;
    float* o = outp + (size_t)Tt*Bb*Vv + (size_t)bid*Hh;
    for (int i = tid; i < Hh; i += 256) o[i] = hr[i];
  }
}

// ---------------- phase 3: decoder GEMM (tf32) ----------------
__global__ void __launch_bounds__(256) dec_kernel(
  const float* __restrict__ decB, float* __restrict__ outp)
{
  extern __shared__ unsigned char smraw[];
  float* Ash = (float*)smraw;
  float* Bsh = (float*)smraw + PIPE*4608;
  const int tid = threadIdx.x;
  const int n0 = blockIdx.x * 128;
  const int m0 = blockIdx.y * 128;
  const int lane = tid & 31, warp = tid >> 5;
  const int wm = (warp & 1) * 64, wn = (warp >> 1) * 32;
  const int g = lane >> 2, tg = lane & 3;
  float acc[4][4][4];
#pragma unroll
  for (int a=0;a<4;a++)
#pragma unroll
    for (int b=0;b<4;b++)
#pragma unroll
      for (int c=0;c<4;c++) acc[a][b][c]=0.f;

  auto load_tile = [&](int p, int kbi){
    int kb = kbi * 32;
#pragma unroll
    for (int i = 0; i < 4; i++){
      int idx = tid + i*256, row = idx>>3, c4 = (idx&7)*4;
      cpa16(&Ash[p*4608 + row*36 + c4], g_OUT + (size_t)(m0+row)*Hh + kb + c4);
      cpa16(&Bsh[p*4608 + row*36 + c4], g_Wd + (size_t)(n0+row)*Hh + kb + c4);
    }
  };

#pragma unroll
  for (int p = 0; p < PIPE-1; p++){ load_tile(p, p); cpa_commit(); }
  for (int it = 0; it < 32; it++){
    cpa_wait<PIPE-2>();
    __syncthreads();
    int nx = it + PIPE - 1;
    if (nx < 32) load_tile(nx % PIPE, nx);
    cpa_commit();
    compute_64x32(Ash + (it%PIPE)*4608, Bsh + (it%PIPE)*4608, acc, wm, wn, g, tg);
  }

#pragma unroll
  for (int mi=0;mi<4;mi++){
    int r = m0 + wm + mi*16 + g;
#pragma unroll
    for (int ni=0;ni<4;ni++){
      int c = n0 + wn + ni*8 + 2*tg;
      if (c < Vv){
        float b0 = decB[c], b1 = decB[c+1];
        size_t o  = (size_t)r*Vv + c;
        size_t o2 = o + (size_t)8*Vv;
        outp[o]    = acc[mi][ni][0] + b0;
        outp[o+1]  = acc[mi][ni][1] + b1;
        outp[o2]   = acc[mi][ni][2] + b0;
        outp[o2+1] = acc[mi][ni][3] + b1;
      }
    }
  }
}

// ---------------- launch ----------------
extern "C" void kernel_launch(void* const* d_in, const int* in_sizes, int n_in,
                              void* d_out, int out_size){
  const int*   tokens = (const int*)  d_in[0];
  const float* embW   = (const float*)d_in[1];
  const float* wxcW   = (const float*)d_in[2];
  const float* wxcB   = (const float*)d_in[3];
  const float* wxhW   = (const float*)d_in[4];
  const float* wxhB   = (const float*)d_in[5];
  const float* w_hc   = (const float*)d_in[6];
  const float* w_hh   = (const float*)d_in[7];
  const float* edge_h = (const float*)d_in[8];
  const float* edge_c = (const float*)d_in[9];
  const float* decW   = (const float*)d_in[10];
  const float* decB   = (const float*)d_in[11];
  float* outp = (float*)d_out;
  (void)in_sizes; (void)n_in; (void)out_size;

  const int RNN_SMEM  = (2*36864 + 2*18432) * 2;   // 221184 B (halves)
  const int GEMM_SMEM = PIPE * 2 * 4608 * 4;       // 110592 B (floats, tf32)
  cudaFuncSetAttribute(xproj_kernel, cudaFuncAttributeMaxDynamicSharedMemorySize, GEMM_SMEM);
  cudaFuncSetAttribute(rnn_kernel,   cudaFuncAttributeMaxDynamicSharedMemorySize, RNN_SMEM);
  cudaFuncSetAttribute(dec_kernel,   cudaFuncAttributeMaxDynamicSharedMemorySize, GEMM_SMEM);

  // reset barrier flags
  void *pArr = nullptr, *pRel = nullptr;
  cudaGetSymbolAddress(&pArr, g_arr);
  cudaGetSymbolAddress(&pRel, g_rel);
  cudaMemsetAsync(pArr, 0, sizeof(unsigned)*GRID_R);
  cudaMemsetAsync(pRel, 0, sizeof(unsigned));

  const long PREP_TOTAL = S_WC + S_WH + S_WE + S_WX + S_WD;
  prep_all<<<(unsigned)((PREP_TOTAL + 255) / 256), 256>>>(
      w_hc, edge_c, w_hh, edge_h, embW, wxcW, wxhW, decW);

  xproj_kernel<<<dim3(8, 64, 2), 256, GEMM_SMEM>>>(tokens, wxcB, wxhB);
  rnn_kernel<<<GRID_R, 256, RNN_SMEM>>>(outp);
  dec_kernel<<<dim3(VPAD/128, 64), 256, GEMM_SMEM>>>(decB, outp);
}

// round 12
// speedup vs baseline: 1.5779x; 1.0117x over previous
#include <cuda_runtime.h>
#include <cuda_fp16.h>
#include <math.h>

#define Tt   64
#define Bb   128
#define Ee   1024
#define Hh   1024
#define Vv   10000
#define NBLK 12
#define GRID_R 128
#define VPAD 10112
#define PIPE 3

// ---------------- scratch (device globals) ----------------
__device__ __align__(16) float  g_XC[Tt*Bb*Hh];     // x @ wxc^T + b (f32, tf32 GEMM)
__device__ __align__(16) float  g_XH[Tt*Bb*Hh];
__device__ __align__(16) float  g_OUT[Tt*Bb*Hh];    // tf32-rounded pre-clip hidden (decoder A)
__device__ __align__(16) float  g_Hf[2*Bb*Hh];      // carried hidden f32, stage-parity double buffer
__device__ __align__(16) __half g_Hh2[2*Bb*Hh];     // fp16 twin (recurrence GEMM A), double buffer
__device__ __align__(16) __half g_Wc[NBLK*Hh*Hh];   // fp16 [w_hc, edge_c x11]  (gate)
__device__ __align__(16) __half g_Wh[NBLK*Hh*Hh];   // fp16 [w_hh, edge_h x11]  (candidate)
__device__ __align__(16) float  g_We[Vv*Ee];        // tf32 embedding
__device__ __align__(16) float  g_Wx[2*Hh*Ee];      // tf32 wxc, wxh
__device__ __align__(16) float  g_Wd[VPAD*Hh];      // tf32 + zero-padded dec_W
__device__ unsigned g_arr[GRID_R];
__device__ unsigned g_rel;

// ---------------- helpers ----------------
__device__ __forceinline__ unsigned f2tf32(float x){
  unsigned u; asm("cvt.rna.tf32.f32 %0, %1;" : "=r"(u) : "f"(x)); return u;
}
__device__ __forceinline__ float rndtf(float x){ return __uint_as_float(f2tf32(x)); }

__device__ __forceinline__ uint2 pack4h(float4 v){
  __half2 a = __floats2half2_rn(v.x, v.y);
  __half2 b = __floats2half2_rn(v.z, v.w);
  uint2 u;
  u.x = *(unsigned*)&a;
  u.y = *(unsigned*)&b;
  return u;
}

__device__ __forceinline__ void mma_tf32(float* c, const unsigned* a, const unsigned* b){
  asm volatile(
    "mma.sync.aligned.m16n8k8.row.col.f32.tf32.tf32.f32 "
    "{%0,%1,%2,%3}, {%4,%5,%6,%7}, {%8,%9}, {%0,%1,%2,%3};\n"
    : "+f"(c[0]), "+f"(c[1]), "+f"(c[2]), "+f"(c[3])
    : "r"(a[0]), "r"(a[1]), "r"(a[2]), "r"(a[3]), "r"(b[0]), "r"(b[1]));
}

__device__ __forceinline__ void mma_fp16(float* c, const unsigned* a, const unsigned* b){
  asm volatile(
    "mma.sync.aligned.m16n8k16.row.col.f32.f16.f16.f32 "
    "{%0,%1,%2,%3}, {%4,%5,%6,%7}, {%8,%9}, {%0,%1,%2,%3};\n"
    : "+f"(c[0]), "+f"(c[1]), "+f"(c[2]), "+f"(c[3])
    : "r"(a[0]), "r"(a[1]), "r"(a[2]), "r"(a[3]), "r"(b[0]), "r"(b[1]));
}

__device__ __forceinline__ void ldsm4(unsigned* r, unsigned a){
  asm volatile("ldmatrix.sync.aligned.m8n8.x4.shared.b16 {%0,%1,%2,%3}, [%4];"
    : "=r"(r[0]), "=r"(r[1]), "=r"(r[2]), "=r"(r[3]) : "r"(a));
}

__device__ __forceinline__ void cpa16(void* smemp, const void* gmem){
  unsigned s = (unsigned)__cvta_generic_to_shared(smemp);
  asm volatile("cp.async.cg.shared.global [%0], [%1], 16;\n" :: "r"(s), "l"(gmem));
}
__device__ __forceinline__ void cpa_commit(){ asm volatile("cp.async.commit_group;\n"); }
template<int N> __device__ __forceinline__ void cpa_wait(){
  asm volatile("cp.async.wait_group %0;\n" :: "n"(N));
}

__device__ __forceinline__ float sigm(float x){ return 1.f/(1.f + expf(-x)); }

// grid barrier (two-hop): per-CTA flag words, CTA0 scans, single release word.
__device__ __forceinline__ void gsync(unsigned &ep){
  ep++;
  __syncthreads();
  if (blockIdx.x == 0){
    if (threadIdx.x > 0 && threadIdx.x < GRID_R){
      while (*(volatile unsigned*)&g_arr[threadIdx.x] < ep) { }
    }
    __syncthreads();
    if (threadIdx.x == 0){ __threadfence(); *(volatile unsigned*)&g_rel = ep; }
  } else {
    if (threadIdx.x == 0){
      __threadfence();
      *(volatile unsigned*)&g_arr[blockIdx.x] = ep;
      while (*(volatile unsigned*)&g_rel < ep) { }
    }
  }
  __syncthreads();
  __threadfence();
}

// tf32 warp tile 64x32 (mi4 x ni4), k-block 32 floats, smem row stride 36 u32
__device__ __forceinline__ void compute_64x32(const float* Af, const float* Bf,
      float acc[4][4][4], int wm, int wn, int g, int tg){
  const unsigned* As = (const unsigned*)Af;
  const unsigned* Bs = (const unsigned*)Bf;
#pragma unroll
  for (int ks = 0; ks < 32; ks += 8){
    unsigned a[4][4], b[4][2];
#pragma unroll
    for (int mi = 0; mi < 4; mi++){
      int r = wm + mi*16 + g;
      a[mi][0] = As[r*36 + ks+tg];
      a[mi][1] = As[(r+8)*36 + ks+tg];
      a[mi][2] = As[r*36 + ks+tg+4];
      a[mi][3] = As[(r+8)*36 + ks+tg+4];
    }
#pragma unroll
    for (int ni = 0; ni < 4; ni++){
      int rr = wn + ni*8 + g;
      b[ni][0] = Bs[rr*36 + ks+tg];
      b[ni][1] = Bs[rr*36 + ks+tg+4];
    }
#pragma unroll
    for (int mi = 0; mi < 4; mi++)
#pragma unroll
      for (int ni = 0; ni < 4; ni++)
        mma_tf32(acc[mi][ni], a[mi], b[ni]);
  }
}

// fp16: one 64-k block via ldmatrix, warp tile 16(M)x8(N), BOTH mats share A fragments.
// abase/cbase/hbase are per-lane smem byte addresses (see lane-offset setup in rnn_kernel).
__device__ __forceinline__ void compute_blk_ldsm(unsigned abase, unsigned cbase, unsigned hbase,
      float accc[4], float acch[4]){
  unsigned a[4][4];
#pragma unroll
  for (int ks = 0; ks < 4; ks++) ldsm4(a[ks], abase + ks*32);   // +16 halves per k16
  unsigned qc[2][4], qh[2][4];
  ldsm4(qc[0], cbase);        // covers ks 0,1 (b0,b1 each)
  ldsm4(qc[1], cbase + 64);   // covers ks 2,3
  ldsm4(qh[0], hbase);
  ldsm4(qh[1], hbase + 64);
#pragma unroll
  for (int ks = 0; ks < 4; ks++){
    mma_fp16(accc, a[ks], &qc[ks>>1][(ks&1)*2]);
    mma_fp16(acch, a[ks], &qh[ks>>1][(ks&1)*2]);
  }
}

// ---------------- prep: wc/wh -> fp16, we/wx/wd -> tf32 ----------------
#define S_WC  3145728L
#define S_WH  3145728L
#define S_WE  2560000L
#define S_WX   524288L
#define S_WD  2588672L
__global__ void __launch_bounds__(256) prep_all(
    const float* __restrict__ w_hc, const float* __restrict__ edge_c,
    const float* __restrict__ w_hh, const float* __restrict__ edge_h,
    const float* __restrict__ embW, const float* __restrict__ wxcW,
    const float* __restrict__ wxhW, const float* __restrict__ decW)
{
  long i = (long)blockIdx.x*256 + threadIdx.x;
  const long F4 = (long)Hh*Hh/4;
  if (i < S_WC){
    float4 v = (i < F4) ? ((const float4*)w_hc)[i] : ((const float4*)edge_c)[i-F4];
    ((uint2*)g_Wc)[i] = pack4h(v);
    return;
  }
  if ((i -= S_WC) < S_WH){
    float4 v = (i < F4) ? ((const float4*)w_hh)[i] : ((const float4*)edge_h)[i-F4];
    ((uint2*)g_Wh)[i] = pack4h(v);
    return;
  }
  float4 v; float4* dst;
  if ((i -= S_WH) < S_WE){
    v = ((const float4*)embW)[i];
    dst = ((float4*)g_We) + i;
  } else if ((i -= S_WE) < S_WX){
    const long G4 = (long)Hh*Ee/4;
    v = (i < G4) ? ((const float4*)wxcW)[i] : ((const float4*)wxhW)[i-G4];
    dst = ((float4*)g_Wx) + i;
  } else if ((i -= S_WX) < S_WD){
    long row = (i*4) >> 10;
    v = (row < Vv) ? ((const float4*)decW)[i] : make_float4(0.f,0.f,0.f,0.f);
    dst = ((float4*)g_Wd) + i;
  } else return;
  float4 r; r.x=rndtf(v.x); r.y=rndtf(v.y); r.z=rndtf(v.z); r.w=rndtf(v.w);
  *dst = r;
}

// ---------------- phase 1: input projections (tf32) ----------------
__global__ void __launch_bounds__(256) xproj_kernel(
    const int* __restrict__ tokens,
    const float* __restrict__ wxcB, const float* __restrict__ wxhB)
{
  extern __shared__ unsigned char smraw[];
  float* Ash = (float*)smraw;               // PIPE * 128*36 floats
  float* Bsh = (float*)smraw + PIPE*4608;   // PIPE * 128*36 floats
  __shared__ int toks[128];
  const int tid = threadIdx.x;
  const int n0 = blockIdx.x * 128;
  const int m0 = blockIdx.y * 128;
  const int mat = blockIdx.z;
  const float* W    = g_Wx + (size_t)mat*Hh*Ee;
  const float* bias = mat ? wxhB : wxcB;
  float* Cout = mat ? g_XH : g_XC;
  if (tid < 128) toks[tid] = tokens[m0 + tid];
  __syncthreads();
  const int lane = tid & 31, warp = tid >> 5;
  const int wm = (warp & 1) * 64, wn = (warp >> 1) * 32;
  const int g = lane >> 2, tg = lane & 3;

  float acc[4][4][4];
#pragma unroll
  for (int a=0;a<4;a++)
#pragma unroll
    for (int b=0;b<4;b++)
#pragma unroll
      for (int c=0;c<4;c++) acc[a][b][c]=0.f;

  auto load_tile = [&](int p, int kbi){
    int kb = kbi * 32;
#pragma unroll
    for (int i = 0; i < 4; i++){
      int idx = tid + i*256, row = idx>>3, c4 = (idx&7)*4;
      cpa16(&Ash[p*4608 + row*36 + c4], g_We + (size_t)toks[row]*Ee + kb + c4);
      cpa16(&Bsh[p*4608 + row*36 + c4], W + (size_t)(n0+row)*Ee + kb + c4);
    }
  };

#pragma unroll
  for (int p = 0; p < PIPE-1; p++){ load_tile(p, p); cpa_commit(); }
  for (int it = 0; it < 32; it++){
    cpa_wait<PIPE-2>();
    __syncthreads();
    int nx = it + PIPE - 1;
    if (nx < 32) load_tile(nx % PIPE, nx);
    cpa_commit();
    compute_64x32(Ash + (it%PIPE)*4608, Bsh + (it%PIPE)*4608, acc, wm, wn, g, tg);
  }

#pragma unroll
  for (int mi=0; mi<4; mi++){
    int r = m0 + wm + mi*16 + g;
#pragma unroll
    for (int ni=0; ni<4; ni++){
      int c = n0 + wn + ni*8 + 2*tg;
      float b0 = bias[c], b1 = bias[c+1];
      size_t o = (size_t)r*Hh + c;
      Cout[o]        = acc[mi][ni][0] + b0;
      Cout[o+1]      = acc[mi][ni][1] + b1;
      Cout[o+8*Hh]   = acc[mi][ni][2] + b0;
      Cout[o+8*Hh+1] = acc[mi][ni][3] + b1;
    }
  }
}

// ---------------- phase 2: persistent recurrence (fp16 mma, fused gate, ldmatrix) ----------------
// 128 CTAs, CTA bid owns N columns [bid*8, bid*8+8) for BOTH mats, full K=1024.
// A (hidden, fp16) streamed in 4 chunks of 128x256, ping-pong smem buffers.
// B (both mats, 8x1024 each) resident; next stage's B prefetched during mainloop.
// Epilogue computes gate+blend in registers; ONE grid barrier per stage.
__global__ void __launch_bounds__(256) rnn_kernel(float* __restrict__ outp)
{
  extern __shared__ unsigned char smraw[];
  __half* Aw = (__half*)smraw;               // 2 x 36864 halves (2 chunks of 4 blocks [128][72])
  __half* Bw = (__half*)smraw + 73728;       // 2 x 18432 halves (2 stages x 2 mats x 16 blocks [8][72])
  __shared__ float red[9];
  const int tid = threadIdx.x;
  const int bid = blockIdx.x;
  const int lane = tid & 31, warp = tid >> 5;
  const int wm = warp * 16;
  const int g = lane >> 2, tg = lane & 3;
  const int n0 = bid * 8;
  const int r0 = wm + g, r1 = wm + g + 8;
  const int c0 = n0 + 2*tg;
  unsigned ep = 0;

  // ldmatrix per-lane byte offsets (j = lane/8, r = lane%8):
  //   A:  row = wm + r + ((j&1)<<3), half-col = ((j>>1)<<3)
  //   B:  row = r (n index), half-col = j*8
  const unsigned sA = (unsigned)__cvta_generic_to_shared(Aw);
  const unsigned sB = (unsigned)__cvta_generic_to_shared(Bw);
  const int lj = lane >> 3, lr = lane & 7;
  const unsigned aoff = (unsigned)(((wm + lr + ((lj&1)<<3))*72 + ((lj>>1)<<3)) * 2);
  const unsigned boff = (unsigned)((lr*72 + lj*8) * 2);

  auto load_A = [&](int par, int kb, int p){   // chunk kb (0..3) of h buffer par
    const __half* src = g_Hh2 + (size_t)par*Bb*Hh;
#pragma unroll
    for (int i = 0; i < 16; i++){
      int idx = tid + i*256;                   // 4096 cpa16 per chunk
      int row = idx >> 5;
      int kh  = (idx & 31) * 8;                // half offset within 256-k chunk
      int blk = kh >> 6, kk = kh & 63;
      cpa16(&Aw[p*36864 + blk*9216 + row*72 + kk],
            src + (size_t)row*Hh + kb*256 + kh);
    }
  };
  auto load_B = [&](int s, int q){
#pragma unroll
    for (int i = 0; i < 8; i++){
      int idx = tid + i*256;                   // 2048 cpa16 per stage (both mats)
      int m2 = idx >> 10;
      int j  = idx & 1023;
      int blk = j >> 6;                        // 0..15
      int jj = j & 63;
      int row = jj >> 3, c8 = (jj & 7) * 8;
      const __half* W = (m2 ? g_Wh : g_Wc) + (size_t)s*Hh*Hh;
      cpa16(&Bw[q*18432 + m2*9216 + blk*576 + row*72 + c8],
            W + (size_t)(n0+row)*Hh + blk*64 + c8);
    }
  };

  // prologue: stage-0 weights; zero h buffer 0 (f32 + fp16)
  load_B(0, 0); cpa_commit();
  {
    int i4 = bid*256 + tid;                    // 32768 float4 = buffer 0 of g_Hf
    ((float4*)g_Hf)[i4] = make_float4(0.f,0.f,0.f,0.f);
    if (i4 < Bb*Hh/8){                         // 16384 uint2 = buffer 0 of g_Hh2
      uint2 z; z.x = 0u; z.y = 0u;
      ((uint2*)g_Hh2)[i4] = z;
    }
  }
  gsync(ep);

  for (int t = 0; t < Tt; t++){
    for (int s = 0; s < NBLK; s++){
      const int par = s & 1;                   // h & B buffers for this stage
      // byte bases for this stage's B (gate / candidate), lane-adjusted
      const unsigned cb0 = sB + (unsigned)(par*18432*2) + boff;
      const unsigned hb0 = cb0 + (unsigned)(9216*2);

      float accc[4] = {0.f,0.f,0.f,0.f};
      float acch[4] = {0.f,0.f,0.f,0.f};

      // issue: A0, A1, next-stage B
      load_A(par, 0, 0); cpa_commit();
      load_A(par, 1, 1); cpa_commit();
      {
        int sn = s + 1; if (sn == NBLK) sn = 0;
        load_B(sn, par ^ 1); cpa_commit();
      }

      // iter 0: chunk 0 (blocks 0..3)
      cpa_wait<2>(); __syncthreads();
#pragma unroll
      for (int b = 0; b < 4; b++)
        compute_blk_ldsm(sA + (unsigned)(0*36864 + b*9216)*2 + aoff,
                         cb0 + (unsigned)((0*4+b)*576)*2,
                         hb0 + (unsigned)((0*4+b)*576)*2, accc, acch);
      __syncthreads();
      load_A(par, 2, 0); cpa_commit();

      // iter 1: chunk 1 (blocks 4..7)
      cpa_wait<2>(); __syncthreads();
#pragma unroll
      for (int b = 0; b < 4; b++)
        compute_blk_ldsm(sA + (unsigned)(1*36864 + b*9216)*2 + aoff,
                         cb0 + (unsigned)((1*4+b)*576)*2,
                         hb0 + (unsigned)((1*4+b)*576)*2, accc, acch);
      __syncthreads();
      load_A(par, 3, 1); cpa_commit();

      // iter 2: chunk 2 (blocks 8..11)
      cpa_wait<1>(); __syncthreads();
#pragma unroll
      for (int b = 0; b < 4; b++)
        compute_blk_ldsm(sA + (unsigned)(0*36864 + b*9216)*2 + aoff,
                         cb0 + (unsigned)((2*4+b)*576)*2,
                         hb0 + (unsigned)((2*4+b)*576)*2, accc, acch);

      // iter 3: chunk 3 (blocks 12..15); wait<0> also guarantees next-stage B landed
      cpa_wait<0>(); __syncthreads();
#pragma unroll
      for (int b = 0; b < 4; b++)
        compute_blk_ldsm(sA + (unsigned)(1*36864 + b*9216)*2 + aoff,
                         cb0 + (unsigned)((3*4+b)*576)*2,
                         hb0 + (unsigned)((3*4+b)*576)*2, accc, acch);

      // fused epilogue: gate + activation + blend for this thread's 4 elements
      {
        const int np = par ^ 1;
        const float* Hprev = g_Hf + (size_t)par*Bb*Hh;
        float*       Hnext = g_Hf + (size_t)np *Bb*Hh;
        __half*      Hh16  = g_Hh2 + (size_t)np*Bb*Hh;

        float sc0=accc[0], sc1=accc[1], sc2=accc[2], sc3=accc[3];
        float sh0=acch[0], sh1=acch[1], sh2=acch[2], sh3=acch[3];
        if (s == 0){
          const float* XCb = g_XC + ((size_t)t<<17);
          const float* XHb = g_XH + ((size_t)t<<17);
          float2 a0 = *(const float2*)(XCb + (size_t)r0*Hh + c0);
          float2 a1 = *(const float2*)(XCb + (size_t)r1*Hh + c0);
          float2 b0 = *(const float2*)(XHb + (size_t)r0*Hh + c0);
          float2 b1 = *(const float2*)(XHb + (size_t)r1*Hh + c0);
          sc0 += a0.x; sc1 += a0.y; sc2 += a1.x; sc3 += a1.y;
          sh0 += b0.x; sh1 += b0.y; sh2 += b1.x; sh3 += b1.y;
        }
        float2 h0 = *(const float2*)(Hprev + (size_t)r0*Hh + c0);
        float2 h1 = *(const float2*)(Hprev + (size_t)r1*Hh + c0);
        const bool use_tanh = (s == 0) || (s & 1);
        float g0 = sigm(sc0), g1 = sigm(sc1), g2 = sigm(sc2), g3 = sigm(sc3);
        float a0 = use_tanh ? tanhf(sh0) : fmaxf(sh0, 0.f);
        float a1 = use_tanh ? tanhf(sh1) : fmaxf(sh1, 0.f);
        float a2 = use_tanh ? tanhf(sh2) : fmaxf(sh2, 0.f);
        float a3 = use_tanh ? tanhf(sh3) : fmaxf(sh3, 0.f);
        float n0v = g0*a0 + (1.f-g0)*h0.x;
        float n1v = g1*a1 + (1.f-g1)*h0.y;
        float n2v = g2*a2 + (1.f-g2)*h1.x;
        float n3v = g3*a3 + (1.f-g3)*h1.y;
        *(float2*)(Hnext + (size_t)r0*Hh + c0) = make_float2(n0v, n1v);
        *(float2*)(Hnext + (size_t)r1*Hh + c0) = make_float2(n2v, n3v);
        __half2 p0 = __floats2half2_rn(n0v, n1v);
        __half2 p1 = __floats2half2_rn(n2v, n3v);
        *(unsigned*)(Hh16 + (size_t)r0*Hh + c0) = *(unsigned*)&p0;
        *(unsigned*)(Hh16 + (size_t)r1*Hh + c0) = *(unsigned*)&p1;
        if (s == NBLK-1){
          float* Ob = g_OUT + ((size_t)t<<17);
          *(float2*)(Ob + (size_t)r0*Hh + c0) = make_float2(rndtf(n0v), rndtf(n1v));
          *(float2*)(Ob + (size_t)r1*Hh + c0) = make_float2(rndtf(n2v), rndtf(n3v));
        }
      }
      gsync(ep);
    }

    // per-row norm clip on buffer 0 (h written at s=11 lands in buf 0); CTA bid owns row bid
    {
      float*  hr = g_Hf  + (size_t)bid * Hh;
      __half* hh = g_Hh2 + (size_t)bid * Hh;
      float ss = 0.f;
      for (int i = tid; i < Hh; i += 256){ float v = hr[i]; ss += v*v; }
#pragma unroll
      for (int off = 16; off > 0; off >>= 1) ss += __shfl_xor_sync(0xffffffffu, ss, off);
      if (lane == 0) red[warp] = ss;
      __syncthreads();
      if (tid == 0){
        float tot = 0.f;
#pragma unroll
        for (int w2 = 0; w2 < 8; w2++) tot += red[w2];
        float nrm = sqrtf(tot);
        red[8] = (nrm > 25.f) ? (25.f / nrm) : 1.f;
      }
      __syncthreads();
      float scl = red[8];
      if (scl != 1.f){
        for (int i = tid; i < Hh; i += 256){
          float v = hr[i] * scl;
          hr[i] = v;
          hh[i] = __float2half_rn(v);
        }
      }
    }
    gsync(ep);
  }

  // hT (clipped final hidden, buffer 0) appended after decoded
  {
    const float* hr = g_Hf + (size_t)bid * Hh;
    float* o = outp + (size_t)Tt*Bb*Vv + (size_t)bid*Hh;
    for (int i = tid; i < Hh; i += 256) o[i] = hr[i];
  }
}

// ---------------- phase 3: decoder GEMM (tf32) ----------------
__global__ void __launch_bounds__(256) dec_kernel(
  const float* __restrict__ decB, float* __restrict__ outp)
{
  extern __shared__ unsigned char smraw[];
  float* Ash = (float*)smraw;
  float* Bsh = (float*)smraw + PIPE*4608;
  const int tid = threadIdx.x;
  const int n0 = blockIdx.x * 128;
  const int m0 = blockIdx.y * 128;
  const int lane = tid & 31, warp = tid >> 5;
  const int wm = (warp & 1) * 64, wn = (warp >> 1) * 32;
  const int g = lane >> 2, tg = lane & 3;
  float acc[4][4][4];
#pragma unroll
  for (int a=0;a<4;a++)
#pragma unroll
    for (int b=0;b<4;b++)
#pragma unroll
      for (int c=0;c<4;c++) acc[a][b][c]=0.f;

  auto load_tile = [&](int p, int kbi){
    int kb = kbi * 32;
#pragma unroll
    for (int i = 0; i < 4; i++){
      int idx = tid + i*256, row = idx>>3, c4 = (idx&7)*4;
      cpa16(&Ash[p*4608 + row*36 + c4], g_OUT + (size_t)(m0+row)*Hh + kb + c4);
      cpa16(&Bsh[p*4608 + row*36 + c4], g_Wd + (size_t)(n0+row)*Hh + kb + c4);
    }
  };

#pragma unroll
  for (int p = 0; p < PIPE-1; p++){ load_tile(p, p); cpa_commit(); }
  for (int it = 0; it < 32; it++){
    cpa_wait<PIPE-2>();
    __syncthreads();
    int nx = it + PIPE - 1;
    if (nx < 32) load_tile(nx % PIPE, nx);
    cpa_commit();
    compute_64x32(Ash + (it%PIPE)*4608, Bsh + (it%PIPE)*4608, acc, wm, wn, g, tg);
  }

#pragma unroll
  for (int mi=0;mi<4;mi++){
    int r = m0 + wm + mi*16 + g;
#pragma unroll
    for (int ni=0;ni<4;ni++){
      int c = n0 + wn + ni*8 + 2*tg;
      if (c < Vv){
        float b0 = decB[c], b1 = decB[c+1];
        size_t o  = (size_t)r*Vv + c;
        size_t o2 = o + (size_t)8*Vv;
        outp[o]    = acc[mi][ni][0] + b0;
        outp[o+1]  = acc[mi][ni][1] + b1;
        outp[o2]   = acc[mi][ni][2] + b0;
        outp[o2+1] = acc[mi][ni][3] + b1;
      }
    }
  }
}

// ---------------- launch ----------------
extern "C" void kernel_launch(void* const* d_in, const int* in_sizes, int n_in,
                              void* d_out, int out_size){
  const int*   tokens = (const int*)  d_in[0];
  const float* embW   = (const float*)d_in[1];
  const float* wxcW   = (const float*)d_in[2];
  const float* wxcB   = (const float*)d_in[3];
  const float* wxhW   = (const float*)d_in[4];
  const float* wxhB   = (const float*)d_in[5];
  const float* w_hc   = (const float*)d_in[6];
  const float* w_hh   = (const float*)d_in[7];
  const float* edge_h = (const float*)d_in[8];
  const float* edge_c = (const float*)d_in[9];
  const float* decW   = (const float*)d_in[10];
  const float* decB   = (const float*)d_in[11];
  float* outp = (float*)d_out;
  (void)in_sizes; (void)n_in; (void)out_size;

  const int RNN_SMEM  = (2*36864 + 2*18432) * 2;   // 221184 B (halves)
  const int GEMM_SMEM = PIPE * 2 * 4608 * 4;       // 110592 B (floats, tf32)
  cudaFuncSetAttribute(xproj_kernel, cudaFuncAttributeMaxDynamicSharedMemorySize, GEMM_SMEM);
  cudaFuncSetAttribute(rnn_kernel,   cudaFuncAttributeMaxDynamicSharedMemorySize, RNN_SMEM);
  cudaFuncSetAttribute(dec_kernel,   cudaFuncAttributeMaxDynamicSharedMemorySize, GEMM_SMEM);

  // reset barrier flags
  void *pArr = nullptr, *pRel = nullptr;
  cudaGetSymbolAddress(&pArr, g_arr);
  cudaGetSymbolAddress(&pRel, g_rel);
  cudaMemsetAsync(pArr, 0, sizeof(unsigned)*GRID_R);
  cudaMemsetAsync(pRel, 0, sizeof(unsigned));

  const long PREP_TOTAL = S_WC + S_WH + S_WE + S_WX + S_WD;
  prep_all<<<(unsigned)((PREP_TOTAL + 255) / 256), 256>>>(
      w_hc, edge_c, w_hh, edge_h, embW, wxcW, wxhW, decW);

  xproj_kernel<<<dim3(8, 64, 2), 256, GEMM_SMEM>>>(tokens, wxcB, wxhB);
  rnn_kernel<<<GRID_R, 256, RNN_SMEM>>>(outp);
  dec_kernel<<<dim3(VPAD/128, 64), 256, GEMM_SMEM>>>(decB, outp);
}

// round 13
// speedup vs baseline: 1.7416x; 1.1037x over previous
#include <cuda_runtime.h>
#include <cuda_fp16.h>
#include <math.h>

#define Tt   64
#define Bb   128
#define Ee   1024
#define Hh   1024
#define Vv   10000
#define NBLK 12
#define GRID_R 128
#define VPAD 10112
#define PIPE 3

// ---------------- scratch (device globals) ----------------
__device__ __align__(16) float  g_XC[Tt*Bb*Hh];     // x @ wxc^T + b (f32, tf32 GEMM)
__device__ __align__(16) float  g_XH[Tt*Bb*Hh];
__device__ __align__(16) float  g_OUT[Tt*Bb*Hh];    // tf32-rounded pre-clip hidden (decoder A)
__device__ __align__(16) __half g_Hh2[2*Bb*Hh];     // fp16 hidden (GEMM A), stage-parity double buffer
__device__ __align__(16) float  g_pss[Bb*128];      // per-(row, nt*2+wni) norm partials
__device__ __align__(16) __half g_Wc[NBLK*Hh*Hh];   // fp16 [w_hc, edge_c x11]  (gate)
__device__ __align__(16) __half g_Wh[NBLK*Hh*Hh];   // fp16 [w_hh, edge_h x11]  (candidate)
__device__ __align__(16) float  g_We[Vv*Ee];        // tf32 embedding
__device__ __align__(16) float  g_Wx[2*Hh*Ee];      // tf32 wxc, wxh
__device__ __align__(16) float  g_Wd[VPAD*Hh];      // tf32 + zero-padded dec_W
__device__ unsigned g_arr[GRID_R];
__device__ unsigned g_rel;

// ---------------- helpers ----------------
__device__ __forceinline__ unsigned f2tf32(float x){
  unsigned u; asm("cvt.rna.tf32.f32 %0, %1;" : "=r"(u) : "f"(x)); return u;
}
__device__ __forceinline__ float rndtf(float x){ return __uint_as_float(f2tf32(x)); }

__device__ __forceinline__ uint2 pack4h(float4 v){
  __half2 a = __floats2half2_rn(v.x, v.y);
  __half2 b = __floats2half2_rn(v.z, v.w);
  uint2 u;
  u.x = *(unsigned*)&a;
  u.y = *(unsigned*)&b;
  return u;
}

__device__ __forceinline__ void mma_tf32(float* c, const unsigned* a, const unsigned* b){
  asm volatile(
    "mma.sync.aligned.m16n8k8.row.col.f32.tf32.tf32.f32 "
    "{%0,%1,%2,%3}, {%4,%5,%6,%7}, {%8,%9}, {%0,%1,%2,%3};\n"
    : "+f"(c[0]), "+f"(c[1]), "+f"(c[2]), "+f"(c[3])
    : "r"(a[0]), "r"(a[1]), "r"(a[2]), "r"(a[3]), "r"(b[0]), "r"(b[1]));
}

__device__ __forceinline__ void mma_fp16(float* c, const unsigned* a, const unsigned* b){
  asm volatile(
    "mma.sync.aligned.m16n8k16.row.col.f32.f16.f16.f32 "
    "{%0,%1,%2,%3}, {%4,%5,%6,%7}, {%8,%9}, {%0,%1,%2,%3};\n"
    : "+f"(c[0]), "+f"(c[1]), "+f"(c[2]), "+f"(c[3])
    : "r"(a[0]), "r"(a[1]), "r"(a[2]), "r"(a[3]), "r"(b[0]), "r"(b[1]));
}

__device__ __forceinline__ void ldsm4(unsigned* r, unsigned a){
  asm volatile("ldmatrix.sync.aligned.m8n8.x4.shared.b16 {%0,%1,%2,%3}, [%4];"
    : "=r"(r[0]), "=r"(r[1]), "=r"(r[2]), "=r"(r[3]) : "r"(a));
}

__device__ __forceinline__ void cpa16(void* smemp, const void* gmem){
  unsigned s = (unsigned)__cvta_generic_to_shared(smemp);
  asm volatile("cp.async.cg.shared.global [%0], [%1], 16;\n" :: "r"(s), "l"(gmem));
}
__device__ __forceinline__ void cpa_commit(){ asm volatile("cp.async.commit_group;\n"); }
template<int N> __device__ __forceinline__ void cpa_wait(){
  asm volatile("cp.async.wait_group %0;\n" :: "n"(N));
}

__device__ __forceinline__ float sigm(float x){ return 1.f/(1.f + expf(-x)); }

// grid barrier (two-hop): per-CTA flag words, CTA0 scans, single release word.
__device__ __forceinline__ void gsync(unsigned &ep){
  ep++;
  __syncthreads();
  if (blockIdx.x == 0){
    if (threadIdx.x > 0 && threadIdx.x < GRID_R){
      while (*(volatile unsigned*)&g_arr[threadIdx.x] < ep) { }
    }
    __syncthreads();
    if (threadIdx.x == 0){ __threadfence(); *(volatile unsigned*)&g_rel = ep; }
  } else {
    if (threadIdx.x == 0){
      __threadfence();
      *(volatile unsigned*)&g_arr[blockIdx.x] = ep;
      while (*(volatile unsigned*)&g_rel < ep) { }
    }
  }
  __syncthreads();
  __threadfence();
}

// tf32 warp tile 64x32 (mi4 x ni4), k-block 32 floats, smem row stride 36 u32
__device__ __forceinline__ void compute_64x32(const float* Af, const float* Bf,
      float acc[4][4][4], int wm, int wn, int g, int tg){
  const unsigned* As = (const unsigned*)Af;
  const unsigned* Bs = (const unsigned*)Bf;
#pragma unroll
  for (int ks = 0; ks < 32; ks += 8){
    unsigned a[4][4], b[4][2];
#pragma unroll
    for (int mi = 0; mi < 4; mi++){
      int r = wm + mi*16 + g;
      a[mi][0] = As[r*36 + ks+tg];
      a[mi][1] = As[(r+8)*36 + ks+tg];
      a[mi][2] = As[r*36 + ks+tg+4];
      a[mi][3] = As[(r+8)*36 + ks+tg+4];
    }
#pragma unroll
    for (int ni = 0; ni < 4; ni++){
      int rr = wn + ni*8 + g;
      b[ni][0] = Bs[rr*36 + ks+tg];
      b[ni][1] = Bs[rr*36 + ks+tg+4];
    }
#pragma unroll
    for (int mi = 0; mi < 4; mi++)
#pragma unroll
      for (int ni = 0; ni < 4; ni++)
        mma_tf32(acc[mi][ni], a[mi], b[ni]);
  }
}

// fp16: one 64-k block via ldmatrix, warp tile 16(M)x8(N), both mats share A fragments.
__device__ __forceinline__ void compute_blk_ldsm(unsigned abase, unsigned cbase, unsigned hbase,
      float accc[4], float acch[4]){
  unsigned a[4][4];
#pragma unroll
  for (int ks = 0; ks < 4; ks++) ldsm4(a[ks], abase + ks*32);   // +16 halves per k16
  unsigned qc[2][4], qh[2][4];
  ldsm4(qc[0], cbase);        // covers ks 0,1
  ldsm4(qc[1], cbase + 64);   // covers ks 2,3
  ldsm4(qh[0], hbase);
  ldsm4(qh[1], hbase + 64);
#pragma unroll
  for (int ks = 0; ks < 4; ks++){
    mma_fp16(accc, a[ks], &qc[ks>>1][(ks&1)*2]);
    mma_fp16(acch, a[ks], &qh[ks>>1][(ks&1)*2]);
  }
}

// ---------------- prep: wc/wh -> fp16, we/wx/wd -> tf32 ----------------
#define S_WC  3145728L
#define S_WH  3145728L
#define S_WE  2560000L
#define S_WX   524288L
#define S_WD  2588672L
__global__ void __launch_bounds__(256) prep_all(
    const float* __restrict__ w_hc, const float* __restrict__ edge_c,
    const float* __restrict__ w_hh, const float* __restrict__ edge_h,
    const float* __restrict__ embW, const float* __restrict__ wxcW,
    const float* __restrict__ wxhW, const float* __restrict__ decW)
{
  long i = (long)blockIdx.x*256 + threadIdx.x;
  const long F4 = (long)Hh*Hh/4;
  if (i < S_WC){
    float4 v = (i < F4) ? ((const float4*)w_hc)[i] : ((const float4*)edge_c)[i-F4];
    ((uint2*)g_Wc)[i] = pack4h(v);
    return;
  }
  if ((i -= S_WC) < S_WH){
    float4 v = (i < F4) ? ((const float4*)w_hh)[i] : ((const float4*)edge_h)[i-F4];
    ((uint2*)g_Wh)[i] = pack4h(v);
    return;
  }
  float4 v; float4* dst;
  if ((i -= S_WH) < S_WE){
    v = ((const float4*)embW)[i];
    dst = ((float4*)g_We) + i;
  } else if ((i -= S_WE) < S_WX){
    const long G4 = (long)Hh*Ee/4;
    v = (i < G4) ? ((const float4*)wxcW)[i] : ((const float4*)wxhW)[i-G4];
    dst = ((float4*)g_Wx) + i;
  } else if ((i -= S_WX) < S_WD){
    long row = (i*4) >> 10;
    v = (row < Vv) ? ((const float4*)decW)[i] : make_float4(0.f,0.f,0.f,0.f);
    dst = ((float4*)g_Wd) + i;
  } else return;
  float4 r; r.x=rndtf(v.x); r.y=rndtf(v.y); r.z=rndtf(v.z); r.w=rndtf(v.w);
  *dst = r;
}

// ---------------- phase 1: input projections (tf32) ----------------
__global__ void __launch_bounds__(256) xproj_kernel(
    const int* __restrict__ tokens,
    const float* __restrict__ wxcB, const float* __restrict__ wxhB)
{
  extern __shared__ unsigned char smraw[];
  float* Ash = (float*)smraw;
  float* Bsh = (float*)smraw + PIPE*4608;
  __shared__ int toks[128];
  const int tid = threadIdx.x;
  const int n0 = blockIdx.x * 128;
  const int m0 = blockIdx.y * 128;
  const int mat = blockIdx.z;
  const float* W    = g_Wx + (size_t)mat*Hh*Ee;
  const float* bias = mat ? wxhB : wxcB;
  float* Cout = mat ? g_XH : g_XC;
  if (tid < 128) toks[tid] = tokens[m0 + tid];
  __syncthreads();
  const int lane = tid & 31, warp = tid >> 5;
  const int wm = (warp & 1) * 64, wn = (warp >> 1) * 32;
  const int g = lane >> 2, tg = lane & 3;

  float acc[4][4][4];
#pragma unroll
  for (int a=0;a<4;a++)
#pragma unroll
    for (int b=0;b<4;b++)
#pragma unroll
      for (int c=0;c<4;c++) acc[a][b][c]=0.f;

  auto load_tile = [&](int p, int kbi){
    int kb = kbi * 32;
#pragma unroll
    for (int i = 0; i < 4; i++){
      int idx = tid + i*256, row = idx>>3, c4 = (idx&7)*4;
      cpa16(&Ash[p*4608 + row*36 + c4], g_We + (size_t)toks[row]*Ee + kb + c4);
      cpa16(&Bsh[p*4608 + row*36 + c4], W + (size_t)(n0+row)*Ee + kb + c4);
    }
  };

#pragma unroll
  for (int p = 0; p < PIPE-1; p++){ load_tile(p, p); cpa_commit(); }
  for (int it = 0; it < 32; it++){
    cpa_wait<PIPE-2>();
    __syncthreads();
    int nx = it + PIPE - 1;
    if (nx < 32) load_tile(nx % PIPE, nx);
    cpa_commit();
    compute_64x32(Ash + (it%PIPE)*4608, Bsh + (it%PIPE)*4608, acc, wm, wn, g, tg);
  }

#pragma unroll
  for (int mi=0; mi<4; mi++){
    int r = m0 + wm + mi*16 + g;
#pragma unroll
    for (int ni=0; ni<4; ni++){
      int c = n0 + wn + ni*8 + 2*tg;
      float b0 = bias[c], b1 = bias[c+1];
      size_t o = (size_t)r*Hh + c;
      Cout[o]        = acc[mi][ni][0] + b0;
      Cout[o+1]      = acc[mi][ni][1] + b1;
      Cout[o+8*Hh]   = acc[mi][ni][2] + b0;
      Cout[o+8*Hh+1] = acc[mi][ni][3] + b1;
    }
  }
}

// ---------------- phase 2: persistent recurrence ----------------
// 128 CTAs = 2 mrow x 64 nt. CTA: rows [mrow*64,+64), cols [nt*16,+16), BOTH mats, K=1024.
// h carried in registers (thread owns same (r,c) every stage); fp16 twin double-buffered.
// A streamed in 4 chunks of 64x256 (2 ping-pong buffers); B full-stage double-buffered.
// Fused gate epilogue; one grid barrier per stage (+2 extra at timestep end for norm clip).
__global__ void __launch_bounds__(256) rnn_kernel(float* __restrict__ outp)
{
  extern __shared__ unsigned char smraw[];
  __half* Aw = (__half*)smraw;               // 2 x 18432 halves (chunk = 4 blocks [64][72])
  __half* Bw = (__half*)smraw + 2*18432;     // 2 x 36864 halves (stage = 2 mats x 16 blocks [16][72])
  const int tid = threadIdx.x;
  const int bid = blockIdx.x;
  const int lane = tid & 31, warp = tid >> 5;
  const int wm = (warp & 3) * 16;            // M tile within 64-row slab
  const int wn = (warp >> 2) * 8;            // N tile within 16 cols
  const int wni = warp >> 2;
  const int g = lane >> 2, tg = lane & 3;
  const int mrow = bid >> 6;                 // 0/1
  const int nt   = bid & 63;
  const int rbase = mrow * 64;
  const int n0 = nt * 16;
  const int r0 = rbase + wm + g, r1 = r0 + 8;
  const int c0 = n0 + wn + 2*tg;
  unsigned ep = 0;

  const unsigned sA = (unsigned)__cvta_generic_to_shared(Aw);
  const unsigned sB = (unsigned)__cvta_generic_to_shared(Bw);
  const int lj = lane >> 3, lr = lane & 7;
  const unsigned aoff = (unsigned)(((wm + lr + ((lj&1)<<3))*72 + ((lj>>1)<<3)) * 2);
  const unsigned boff = (unsigned)(((wn + lr)*72 + lj*8) * 2);

  auto load_A = [&](int par, int kb, int p){   // chunk kb (0..3): 64 rows x 256 k
    const __half* src = g_Hh2 + (size_t)par*Bb*Hh + (size_t)rbase*Hh;
#pragma unroll
    for (int i = 0; i < 8; i++){
      int idx = tid + i*256;                   // 2048 cpa16
      int row = idx >> 5;
      int kh  = (idx & 31) * 8;
      int blk = kh >> 6, kk = kh & 63;
      cpa16(&Aw[p*18432 + blk*4608 + row*72 + kk],
            src + (size_t)row*Hh + kb*256 + kh);
    }
  };
  auto load_B = [&](int s, int q){             // both mats, 16 n-rows x 1024 k
#pragma unroll
    for (int i = 0; i < 16; i++){
      int idx = tid + i*256;                   // 4096 cpa16
      int m2 = idx >> 11;
      int j  = idx & 2047;
      int blk = j >> 7;                        // 0..15
      int jj = j & 127;
      int row = jj >> 3, c8 = (jj & 7) * 8;
      const __half* W = (m2 ? g_Wh : g_Wc) + (size_t)s*Hh*Hh;
      cpa16(&Bw[q*36864 + m2*18432 + blk*1152 + row*72 + c8],
            W + (size_t)(n0+row)*Hh + blk*64 + c8);
    }
  };

  float hp0 = 0.f, hp1 = 0.f, hp2 = 0.f, hp3 = 0.f;   // carried hidden (registers)

  // prologue: stage-0 weights; zero fp16 hidden buffer 0
  load_B(0, 0); cpa_commit();
  {
    uint2 z; z.x = 0u; z.y = 0u;
    ((uint2*)g_Hh2)[bid*256 + tid] = z;        // 32768 uint2 = buffer 0
  }
  gsync(ep);

  for (int t = 0; t < Tt; t++){
    for (int s = 0; s < NBLK; s++){
      const int par = s & 1;
      const unsigned cbB = sB + (unsigned)(par*36864*2) + boff;   // gate (Wc)
      const unsigned hbB = cbB + (unsigned)(18432*2);             // cand (Wh)

      float accc[4] = {0.f,0.f,0.f,0.f};
      float acch[4] = {0.f,0.f,0.f,0.f};

      load_A(par, 0, 0); cpa_commit();
      load_A(par, 1, 1); cpa_commit();
      {
        int sn = s + 1; if (sn == NBLK) sn = 0;
        load_B(sn, par ^ 1); cpa_commit();
      }

      // chunk 0 (blocks 0..3)
      cpa_wait<2>(); __syncthreads();
#pragma unroll
      for (int b = 0; b < 4; b++)
        compute_blk_ldsm(sA + (unsigned)(0*18432 + b*4608)*2 + aoff,
                         cbB + (unsigned)((0*4+b)*1152)*2,
                         hbB + (unsigned)((0*4+b)*1152)*2, accc, acch);
      __syncthreads();
      load_A(par, 2, 0); cpa_commit();

      // chunk 1 (blocks 4..7)
      cpa_wait<2>(); __syncthreads();
#pragma unroll
      for (int b = 0; b < 4; b++)
        compute_blk_ldsm(sA + (unsigned)(1*18432 + b*4608)*2 + aoff,
                         cbB + (unsigned)((1*4+b)*1152)*2,
                         hbB + (unsigned)((1*4+b)*1152)*2, accc, acch);
      __syncthreads();
      load_A(par, 3, 1); cpa_commit();

      // chunk 2 (blocks 8..11)
      cpa_wait<1>(); __syncthreads();
#pragma unroll
      for (int b = 0; b < 4; b++)
        compute_blk_ldsm(sA + (unsigned)(0*18432 + b*4608)*2 + aoff,
                         cbB + (unsigned)((2*4+b)*1152)*2,
                         hbB + (unsigned)((2*4+b)*1152)*2, accc, acch);

      // chunk 3 (blocks 12..15); wait<0> also covers next-stage B
      cpa_wait<0>(); __syncthreads();
#pragma unroll
      for (int b = 0; b < 4; b++)
        compute_blk_ldsm(sA + (unsigned)(1*18432 + b*4608)*2 + aoff,
                         cbB + (unsigned)((3*4+b)*1152)*2,
                         hbB + (unsigned)((3*4+b)*1152)*2, accc, acch);

      // fused epilogue
      {
        const int np = par ^ 1;
        __half* Hh16 = g_Hh2 + (size_t)np*Bb*Hh;

        float sc0=accc[0], sc1=accc[1], sc2=accc[2], sc3=accc[3];
        float sh0=acch[0], sh1=acch[1], sh2=acch[2], sh3=acch[3];
        if (s == 0){
          const float* XCb = g_XC + ((size_t)t<<17);
          const float* XHb = g_XH + ((size_t)t<<17);
          float2 a0 = *(const float2*)(XCb + (size_t)r0*Hh + c0);
          float2 a1 = *(const float2*)(XCb + (size_t)r1*Hh + c0);
          float2 b0 = *(const float2*)(XHb + (size_t)r0*Hh + c0);
          float2 b1 = *(const float2*)(XHb + (size_t)r1*Hh + c0);
          sc0 += a0.x; sc1 += a0.y; sc2 += a1.x; sc3 += a1.y;
          sh0 += b0.x; sh1 += b0.y; sh2 += b1.x; sh3 += b1.y;
        }
        const bool use_tanh = (s == 0) || (s & 1);
        float g0 = sigm(sc0), g1 = sigm(sc1), g2 = sigm(sc2), g3 = sigm(sc3);
        float a0 = use_tanh ? tanhf(sh0) : fmaxf(sh0, 0.f);
        float a1 = use_tanh ? tanhf(sh1) : fmaxf(sh1, 0.f);
        float a2 = use_tanh ? tanhf(sh2) : fmaxf(sh2, 0.f);
        float a3 = use_tanh ? tanhf(sh3) : fmaxf(sh3, 0.f);
        float n0v = g0*a0 + (1.f-g0)*hp0;
        float n1v = g1*a1 + (1.f-g1)*hp1;
        float n2v = g2*a2 + (1.f-g2)*hp2;
        float n3v = g3*a3 + (1.f-g3)*hp3;

        if (s < NBLK-1){
          hp0 = n0v; hp1 = n1v; hp2 = n2v; hp3 = n3v;
          __half2 p0 = __floats2half2_rn(n0v, n1v);
          __half2 p1 = __floats2half2_rn(n2v, n3v);
          *(unsigned*)(Hh16 + (size_t)r0*Hh + c0) = *(unsigned*)&p0;
          *(unsigned*)(Hh16 + (size_t)r1*Hh + c0) = *(unsigned*)&p1;
        } else {
          // pre-clip output for decoder
          float* Ob = g_OUT + ((size_t)t<<17);
          *(float2*)(Ob + (size_t)r0*Hh + c0) = make_float2(rndtf(n0v), rndtf(n1v));
          *(float2*)(Ob + (size_t)r1*Hh + c0) = make_float2(rndtf(n2v), rndtf(n3v));
          // norm partials: quad-reduce this thread's 2 cols, leader stores
          float ss0 = n0v*n0v + n1v*n1v;
          float ss1 = n2v*n2v + n3v*n3v;
          ss0 += __shfl_xor_sync(0xffffffffu, ss0, 1);
          ss0 += __shfl_xor_sync(0xffffffffu, ss0, 2);
          ss1 += __shfl_xor_sync(0xffffffffu, ss1, 1);
          ss1 += __shfl_xor_sync(0xffffffffu, ss1, 2);
          if (tg == 0){
            g_pss[r0*128 + nt*2 + wni] = ss0;
            g_pss[r1*128 + nt*2 + wni] = ss1;
          }
          gsync(ep);
          // deterministic row sums
          float t0 = 0.f, t1 = 0.f;
          const float4* q0 = (const float4*)(g_pss + (size_t)r0*128);
          const float4* q1 = (const float4*)(g_pss + (size_t)r1*128);
#pragma unroll
          for (int j = 0; j < 32; j++){
            float4 v = q0[j]; t0 += v.x + v.y + v.z + v.w;
            float4 w = q1[j]; t1 += w.x + w.y + w.z + w.w;
          }
          float nm0 = sqrtf(t0), nm1 = sqrtf(t1);
          float sA0 = (nm0 > 25.f) ? (25.f / nm0) : 1.f;
          float sA1 = (nm1 > 25.f) ? (25.f / nm1) : 1.f;
          hp0 = n0v * sA0; hp1 = n1v * sA0;
          hp2 = n2v * sA1; hp3 = n3v * sA1;
          __half2 p0 = __floats2half2_rn(hp0, hp1);
          __half2 p1 = __floats2half2_rn(hp2, hp3);
          *(unsigned*)(Hh16 + (size_t)r0*Hh + c0) = *(unsigned*)&p0;
          *(unsigned*)(Hh16 + (size_t)r1*Hh + c0) = *(unsigned*)&p1;
        }
      }
      gsync(ep);
    }
  }

  // hT (clipped final hidden, from registers)
  {
    float* o = outp + (size_t)Tt*Bb*Vv;
    *(float2*)(o + (size_t)r0*Hh + c0) = make_float2(hp0, hp1);
    *(float2*)(o + (size_t)r1*Hh + c0) = make_float2(hp2, hp3);
  }
}

// ---------------- phase 3: decoder GEMM (tf32) ----------------
__global__ void __launch_bounds__(256) dec_kernel(
  const float* __restrict__ decB, float* __restrict__ outp)
{
  extern __shared__ unsigned char smraw[];
  float* Ash = (float*)smraw;
  float* Bsh = (float*)smraw + PIPE*4608;
  const int tid = threadIdx.x;
  const int n0 = blockIdx.x * 128;
  const int m0 = blockIdx.y * 128;
  const int lane = tid & 31, warp = tid >> 5;
  const int wm = (warp & 1) * 64, wn = (warp >> 1) * 32;
  const int g = lane >> 2, tg = lane & 3;
  float acc[4][4][4];
#pragma unroll
  for (int a=0;a<4;a++)
#pragma unroll
    for (int b=0;b<4;b++)
#pragma unroll
      for (int c=0;c<4;c++) acc[a][b][c]=0.f;

  auto load_tile = [&](int p, int kbi){
    int kb = kbi * 32;
#pragma unroll
    for (int i = 0; i < 4; i++){
      int idx = tid + i*256, row = idx>>3, c4 = (idx&7)*4;
      cpa16(&Ash[p*4608 + row*36 + c4], g_OUT + (size_t)(m0+row)*Hh + kb + c4);
      cpa16(&Bsh[p*4608 + row*36 + c4], g_Wd + (size_t)(n0+row)*Hh + kb + c4);
    }
  };

#pragma unroll
  for (int p = 0; p < PIPE-1; p++){ load_tile(p, p); cpa_commit(); }
  for (int it = 0; it < 32; it++){
    cpa_wait<PIPE-2>();
    __syncthreads();
    int nx = it + PIPE - 1;
    if (nx < 32) load_tile(nx % PIPE, nx);
    cpa_commit();
    compute_64x32(Ash + (it%PIPE)*4608, Bsh + (it%PIPE)*4608, acc, wm, wn, g, tg);
  }

#pragma unroll
  for (int mi=0;mi<4;mi++){
    int r = m0 + wm + mi*16 + g;
#pragma unroll
    for (int ni=0;ni<4;ni++){
      int c = n0 + wn + ni*8 + 2*tg;
      if (c < Vv){
        float b0 = decB[c], b1 = decB[c+1];
        size_t o  = (size_t)r*Vv + c;
        size_t o2 = o + (size_t)8*Vv;
        outp[o]    = acc[mi][ni][0] + b0;
        outp[o+1]  = acc[mi][ni][1] + b1;
        outp[o2]   = acc[mi][ni][2] + b0;
        outp[o2+1] = acc[mi][ni][3] + b1;
      }
    }
  }
}

// ---------------- launch ----------------
extern "C" void kernel_launch(void* const* d_in, const int* in_sizes, int n_in,
                              void* d_out, int out_size){
  const int*   tokens = (const int*)  d_in[0];
  const float* embW   = (const float*)d_in[1];
  const float* wxcW   = (const float*)d_in[2];
  const float* wxcB   = (const float*)d_in[3];
  const float* wxhW   = (const float*)d_in[4];
  const float* wxhB   = (const float*)d_in[5];
  const float* w_hc   = (const float*)d_in[6];
  const float* w_hh   = (const float*)d_in[7];
  const float* edge_h = (const float*)d_in[8];
  const float* edge_c = (const float*)d_in[9];
  const float* decW   = (const float*)d_in[10];
  const float* decB   = (const float*)d_in[11];
  float* outp = (float*)d_out;
  (void)in_sizes; (void)n_in; (void)out_size;

  const int RNN_SMEM  = (2*18432 + 2*36864) * 2;   // 221184 B
  const int GEMM_SMEM = PIPE * 2 * 4608 * 4;       // 110592 B
  cudaFuncSetAttribute(xproj_kernel, cudaFuncAttributeMaxDynamicSharedMemorySize, GEMM_SMEM);
  cudaFuncSetAttribute(rnn_kernel,   cudaFuncAttributeMaxDynamicSharedMemorySize, RNN_SMEM);
  cudaFuncSetAttribute(dec_kernel,   cudaFuncAttributeMaxDynamicSharedMemorySize, GEMM_SMEM);

  // reset barrier flags
  void *pArr = nullptr, *pRel = nullptr;
  cudaGetSymbolAddress(&pArr, g_arr);
  cudaGetSymbolAddress(&pRel, g_rel);
  cudaMemsetAsync(pArr, 0, sizeof(unsigned)*GRID_R);
  cudaMemsetAsync(pRel, 0, sizeof(unsigned));

  const long PREP_TOTAL = S_WC + S_WH + S_WE + S_WX + S_WD;
  prep_all<<<(unsigned)((PREP_TOTAL + 255) / 256), 256>>>(
      w_hc, edge_c, w_hh, edge_h, embW, wxcW, wxhW, decW);

  xproj_kernel<<<dim3(8, 64, 2), 256, GEMM_SMEM>>>(tokens, wxcB, wxhB);
  rnn_kernel<<<GRID_R, 256, RNN_SMEM>>>(outp);
  dec_kernel<<<dim3(VPAD/128, 64), 256, GEMM_SMEM>>>(decB, outp);
}

// round 14
// speedup vs baseline: 1.7585x; 1.0097x over previous
#include <cuda_runtime.h>
#include <cuda_fp16.h>
#include <math.h>

#define Tt   64
#define Bb   128
#define Ee   1024
#define Hh   1024
#define Vv   10000
#define NBLK 12
#define GRID_R 128
#define VPAD 10112
#define PIPE 2

// ---------------- scratch (device globals) ----------------
__device__ __align__(16) float  g_XC[Tt*Bb*Hh];     // x @ wxc^T + b (f32, tf32 GEMM)
__device__ __align__(16) float  g_XH[Tt*Bb*Hh];
__device__ __align__(16) float  g_OUT[Tt*Bb*Hh];    // tf32-rounded pre-clip hidden (decoder A)
__device__ __align__(16) __half g_Hh2[2*Bb*Hh];     // fp16 hidden (GEMM A), stage-parity double buffer
__device__ __align__(16) float  g_pss[Bb*128];      // per-(row, nt*2+wni) norm partials
__device__ __align__(16) __half g_Wc[NBLK*Hh*Hh];   // fp16 [w_hc, edge_c x11]  (gate)
__device__ __align__(16) __half g_Wh[NBLK*Hh*Hh];   // fp16 [w_hh, edge_h x11]  (candidate)
__device__ __align__(16) float  g_We[Vv*Ee];        // tf32 embedding
__device__ __align__(16) float  g_Wx[2*Hh*Ee];      // tf32 wxc, wxh
__device__ __align__(16) float  g_Wd[VPAD*Hh];      // tf32 + zero-padded dec_W
__device__ unsigned g_arr[GRID_R];
__device__ unsigned g_rel2[2];

// ---------------- helpers ----------------
__device__ __forceinline__ unsigned f2tf32(float x){
  unsigned u; asm("cvt.rna.tf32.f32 %0, %1;" : "=r"(u) : "f"(x)); return u;
}
__device__ __forceinline__ float rndtf(float x){ return __uint_as_float(f2tf32(x)); }

__device__ __forceinline__ uint2 pack4h(float4 v){
  __half2 a = __floats2half2_rn(v.x, v.y);
  __half2 b = __floats2half2_rn(v.z, v.w);
  uint2 u;
  u.x = *(unsigned*)&a;
  u.y = *(unsigned*)&b;
  return u;
}

__device__ __forceinline__ void mma_tf32(float* c, const unsigned* a, const unsigned* b){
  asm volatile(
    "mma.sync.aligned.m16n8k8.row.col.f32.tf32.tf32.f32 "
    "{%0,%1,%2,%3}, {%4,%5,%6,%7}, {%8,%9}, {%0,%1,%2,%3};\n"
    : "+f"(c[0]), "+f"(c[1]), "+f"(c[2]), "+f"(c[3])
    : "r"(a[0]), "r"(a[1]), "r"(a[2]), "r"(a[3]), "r"(b[0]), "r"(b[1]));
}

__device__ __forceinline__ void mma_fp16(float* c, const unsigned* a, const unsigned* b){
  asm volatile(
    "mma.sync.aligned.m16n8k16.row.col.f32.f16.f16.f32 "
    "{%0,%1,%2,%3}, {%4,%5,%6,%7}, {%8,%9}, {%0,%1,%2,%3};\n"
    : "+f"(c[0]), "+f"(c[1]), "+f"(c[2]), "+f"(c[3])
    : "r"(a[0]), "r"(a[1]), "r"(a[2]), "r"(a[3]), "r"(b[0]), "r"(b[1]));
}

__device__ __forceinline__ void ldsm4(unsigned* r, unsigned a){
  asm volatile("ldmatrix.sync.aligned.m8n8.x4.shared.b16 {%0,%1,%2,%3}, [%4];"
    : "=r"(r[0]), "=r"(r[1]), "=r"(r[2]), "=r"(r[3]) : "r"(a));
}

__device__ __forceinline__ void cpa16(void* smemp, const void* gmem){
  unsigned s = (unsigned)__cvta_generic_to_shared(smemp);
  asm volatile("cp.async.cg.shared.global [%0], [%1], 16;\n" :: "r"(s), "l"(gmem));
}
__device__ __forceinline__ void cpa_commit(){ asm volatile("cp.async.commit_group;\n"); }
template<int N> __device__ __forceinline__ void cpa_wait(){
  asm volatile("cp.async.wait_group %0;\n" :: "n"(N));
}

__device__ __forceinline__ float sigm(float x){ return 1.f/(1.f + expf(-x)); }

// group barrier: 64 CTAs of the same mrow (recurrence is row-independent).
// leader CTA (lid==0) scans its group's flags; single release word per group.
__device__ __forceinline__ void gsyncg(unsigned &ep, int mrow, int lid){
  ep++;
  __syncthreads();
  if (lid == 0){
    if (threadIdx.x > 0 && threadIdx.x < 64){
      while (*(volatile unsigned*)&g_arr[mrow*64 + threadIdx.x] < ep) { }
    }
    __syncthreads();
    if (threadIdx.x == 0){ __threadfence(); *(volatile unsigned*)&g_rel2[mrow] = ep; }
  } else {
    if (threadIdx.x == 0){
      __threadfence();
      *(volatile unsigned*)&g_arr[mrow*64 + lid] = ep;
      while (*(volatile unsigned*)&g_rel2[mrow] < ep) { }
    }
  }
  __syncthreads();
  __threadfence();
}

// tf32 warp tile 64x32 (mi4 x ni4), k-block 32 floats, smem row stride 36 u32
__device__ __forceinline__ void compute_64x32(const float* Af, const float* Bf,
      float acc[4][4][4], int wm, int wn, int g, int tg){
  const unsigned* As = (const unsigned*)Af;
  const unsigned* Bs = (const unsigned*)Bf;
#pragma unroll
  for (int ks = 0; ks < 32; ks += 8){
    unsigned a[4][4], b[4][2];
#pragma unroll
    for (int mi = 0; mi < 4; mi++){
      int r = wm + mi*16 + g;
      a[mi][0] = As[r*36 + ks+tg];
      a[mi][1] = As[(r+8)*36 + ks+tg];
      a[mi][2] = As[r*36 + ks+tg+4];
      a[mi][3] = As[(r+8)*36 + ks+tg+4];
    }
#pragma unroll
    for (int ni = 0; ni < 4; ni++){
      int rr = wn + ni*8 + g;
      b[ni][0] = Bs[rr*36 + ks+tg];
      b[ni][1] = Bs[rr*36 + ks+tg+4];
    }
#pragma unroll
    for (int mi = 0; mi < 4; mi++)
#pragma unroll
      for (int ni = 0; ni < 4; ni++)
        mma_tf32(acc[mi][ni], a[mi], b[ni]);
  }
}

// fp16: one 64-k block via ldmatrix, warp tile 16(M)x8(N), both mats share A fragments.
__device__ __forceinline__ void compute_blk_ldsm(unsigned abase, unsigned cbase, unsigned hbase,
      float accc[4], float acch[4]){
  unsigned a[4][4];
#pragma unroll
  for (int ks = 0; ks < 4; ks++) ldsm4(a[ks], abase + ks*32);   // +16 halves per k16
  unsigned qc[2][4], qh[2][4];
  ldsm4(qc[0], cbase);        // covers ks 0,1
  ldsm4(qc[1], cbase + 64);   // covers ks 2,3
  ldsm4(qh[0], hbase);
  ldsm4(qh[1], hbase + 64);
#pragma unroll
  for (int ks = 0; ks < 4; ks++){
    mma_fp16(accc, a[ks], &qc[ks>>1][(ks&1)*2]);
    mma_fp16(acch, a[ks], &qh[ks>>1][(ks&1)*2]);
  }
}

// ---------------- prep: wc/wh -> fp16, we/wx/wd -> tf32 ----------------
#define S_WC  3145728L
#define S_WH  3145728L
#define S_WE  2560000L
#define S_WX   524288L
#define S_WD  2588672L
__global__ void __launch_bounds__(256) prep_all(
    const float* __restrict__ w_hc, const float* __restrict__ edge_c,
    const float* __restrict__ w_hh, const float* __restrict__ edge_h,
    const float* __restrict__ embW, const float* __restrict__ wxcW,
    const float* __restrict__ wxhW, const float* __restrict__ decW)
{
  long i = (long)blockIdx.x*256 + threadIdx.x;
  const long F4 = (long)Hh*Hh/4;
  if (i < S_WC){
    float4 v = (i < F4) ? ((const float4*)w_hc)[i] : ((const float4*)edge_c)[i-F4];
    ((uint2*)g_Wc)[i] = pack4h(v);
    return;
  }
  if ((i -= S_WC) < S_WH){
    float4 v = (i < F4) ? ((const float4*)w_hh)[i] : ((const float4*)edge_h)[i-F4];
    ((uint2*)g_Wh)[i] = pack4h(v);
    return;
  }
  float4 v; float4* dst;
  if ((i -= S_WH) < S_WE){
    v = ((const float4*)embW)[i];
    dst = ((float4*)g_We) + i;
  } else if ((i -= S_WE) < S_WX){
    const long G4 = (long)Hh*Ee/4;
    v = (i < G4) ? ((const float4*)wxcW)[i] : ((const float4*)wxhW)[i-G4];
    dst = ((float4*)g_Wx) + i;
  } else if ((i -= S_WX) < S_WD){
    long row = (i*4) >> 10;
    v = (row < Vv) ? ((const float4*)decW)[i] : make_float4(0.f,0.f,0.f,0.f);
    dst = ((float4*)g_Wd) + i;
  } else return;
  float4 r; r.x=rndtf(v.x); r.y=rndtf(v.y); r.z=rndtf(v.z); r.w=rndtf(v.w);
  *dst = r;
}

// ---------------- phase 1: input projections (tf32, PIPE=2, 3 CTAs/SM) ----------------
__global__ void __launch_bounds__(256) xproj_kernel(
    const int* __restrict__ tokens,
    const float* __restrict__ wxcB, const float* __restrict__ wxhB)
{
  extern __shared__ unsigned char smraw[];
  float* Ash = (float*)smraw;
  float* Bsh = (float*)smraw + PIPE*4608;
  __shared__ int toks[128];
  const int tid = threadIdx.x;
  const int n0 = blockIdx.x * 128;
  const int m0 = blockIdx.y * 128;
  const int mat = blockIdx.z;
  const float* W    = g_Wx + (size_t)mat*Hh*Ee;
  const float* bias = mat ? wxhB : wxcB;
  float* Cout = mat ? g_XH : g_XC;
  if (tid < 128) toks[tid] = tokens[m0 + tid];
  __syncthreads();
  const int lane = tid & 31, warp = tid >> 5;
  const int wm = (warp & 1) * 64, wn = (warp >> 1) * 32;
  const int g = lane >> 2, tg = lane & 3;

  float acc[4][4][4];
#pragma unroll
  for (int a=0;a<4;a++)
#pragma unroll
    for (int b=0;b<4;b++)
#pragma unroll
      for (int c=0;c<4;c++) acc[a][b][c]=0.f;

  auto load_tile = [&](int p, int kbi){
    int kb = kbi * 32;
#pragma unroll
    for (int i = 0; i < 4; i++){
      int idx = tid + i*256, row = idx>>3, c4 = (idx&7)*4;
      cpa16(&Ash[p*4608 + row*36 + c4], g_We + (size_t)toks[row]*Ee + kb + c4);
      cpa16(&Bsh[p*4608 + row*36 + c4], W + (size_t)(n0+row)*Ee + kb + c4);
    }
  };

#pragma unroll
  for (int p = 0; p < PIPE-1; p++){ load_tile(p, p); cpa_commit(); }
  for (int it = 0; it < 32; it++){
    cpa_wait<PIPE-2>();
    __syncthreads();
    int nx = it + PIPE - 1;
    if (nx < 32) load_tile(nx % PIPE, nx);
    cpa_commit();
    compute_64x32(Ash + (it%PIPE)*4608, Bsh + (it%PIPE)*4608, acc, wm, wn, g, tg);
  }

#pragma unroll
  for (int mi=0; mi<4; mi++){
    int r = m0 + wm + mi*16 + g;
#pragma unroll
    for (int ni=0; ni<4; ni++){
      int c = n0 + wn + ni*8 + 2*tg;
      float b0 = bias[c], b1 = bias[c+1];
      size_t o = (size_t)r*Hh + c;
      Cout[o]        = acc[mi][ni][0] + b0;
      Cout[o+1]      = acc[mi][ni][1] + b1;
      Cout[o+8*Hh]   = acc[mi][ni][2] + b0;
      Cout[o+8*Hh+1] = acc[mi][ni][3] + b1;
    }
  }
}

// ---------------- phase 2: persistent recurrence ----------------
// 128 CTAs = 2 mrow x 64 nt. CTA: rows [mrow*64,+64), cols [nt*16,+16), BOTH mats, K=1024.
// h carried in registers; fp16 twin double-buffered. Recurrence is row-independent,
// so all barriers are mrow-local (64 CTAs).
__global__ void __launch_bounds__(256) rnn_kernel(float* __restrict__ outp)
{
  extern __shared__ unsigned char smraw[];
  __half* Aw = (__half*)smraw;               // 2 x 18432 halves (chunk = 4 blocks [64][72])
  __half* Bw = (__half*)smraw + 2*18432;     // 2 x 36864 halves (stage = 2 mats x 16 blocks [16][72])
  const int tid = threadIdx.x;
  const int bid = blockIdx.x;
  const int lane = tid & 31, warp = tid >> 5;
  const int wm = (warp & 3) * 16;
  const int wn = (warp >> 2) * 8;
  const int wni = warp >> 2;
  const int g = lane >> 2, tg = lane & 3;
  const int mrow = bid >> 6;
  const int nt   = bid & 63;
  const int rbase = mrow * 64;
  const int n0 = nt * 16;
  const int r0 = rbase + wm + g, r1 = r0 + 8;
  const int c0 = n0 + wn + 2*tg;
  unsigned ep = 0;

  const unsigned sA = (unsigned)__cvta_generic_to_shared(Aw);
  const unsigned sB = (unsigned)__cvta_generic_to_shared(Bw);
  const int lj = lane >> 3, lr = lane & 7;
  const unsigned aoff = (unsigned)(((wm + lr + ((lj&1)<<3))*72 + ((lj>>1)<<3)) * 2);
  const unsigned boff = (unsigned)(((wn + lr)*72 + lj*8) * 2);

  auto load_A = [&](int par, int kb, int p){   // chunk kb (0..3): 64 rows x 256 k
    const __half* src = g_Hh2 + (size_t)par*Bb*Hh + (size_t)rbase*Hh;
#pragma unroll
    for (int i = 0; i < 8; i++){
      int idx = tid + i*256;
      int row = idx >> 5;
      int kh  = (idx & 31) * 8;
      int blk = kh >> 6, kk = kh & 63;
      cpa16(&Aw[p*18432 + blk*4608 + row*72 + kk],
            src + (size_t)row*Hh + kb*256 + kh);
    }
  };
  auto load_B = [&](int s, int q){             // both mats, 16 n-rows x 1024 k
#pragma unroll
    for (int i = 0; i < 16; i++){
      int idx = tid + i*256;
      int m2 = idx >> 11;
      int j  = idx & 2047;
      int blk = j >> 7;
      int jj = j & 127;
      int row = jj >> 3, c8 = (jj & 7) * 8;
      const __half* W = (m2 ? g_Wh : g_Wc) + (size_t)s*Hh*Hh;
      cpa16(&Bw[q*36864 + m2*18432 + blk*1152 + row*72 + c8],
            W + (size_t)(n0+row)*Hh + blk*64 + c8);
    }
  };

  float hp0 = 0.f, hp1 = 0.f, hp2 = 0.f, hp3 = 0.f;   // carried hidden (registers)

  load_B(0, 0); cpa_commit();
  {
    uint2 z; z.x = 0u; z.y = 0u;
    ((uint2*)g_Hh2)[bid*256 + tid] = z;        // buffer 0 zeros
  }
  gsyncg(ep, mrow, nt);

  for (int t = 0; t < Tt; t++){
    for (int s = 0; s < NBLK; s++){
      const int par = s & 1;
      const unsigned cbB = sB + (unsigned)(par*36864*2) + boff;   // gate (Wc)
      const unsigned hbB = cbB + (unsigned)(18432*2);             // cand (Wh)

      float accc[4] = {0.f,0.f,0.f,0.f};
      float acch[4] = {0.f,0.f,0.f,0.f};

      load_A(par, 0, 0); cpa_commit();
      load_A(par, 1, 1); cpa_commit();
      {
        int sn = s + 1; if (sn == NBLK) sn = 0;
        load_B(sn, par ^ 1); cpa_commit();
      }

      // chunk 0
      cpa_wait<2>(); __syncthreads();
#pragma unroll
      for (int b = 0; b < 4; b++)
        compute_blk_ldsm(sA + (unsigned)(0*18432 + b*4608)*2 + aoff,
                         cbB + (unsigned)((0*4+b)*1152)*2,
                         hbB + (unsigned)((0*4+b)*1152)*2, accc, acch);
      __syncthreads();
      load_A(par, 2, 0); cpa_commit();

      // chunk 1
      cpa_wait<2>(); __syncthreads();
#pragma unroll
      for (int b = 0; b < 4; b++)
        compute_blk_ldsm(sA + (unsigned)(1*18432 + b*4608)*2 + aoff,
                         cbB + (unsigned)((1*4+b)*1152)*2,
                         hbB + (unsigned)((1*4+b)*1152)*2, accc, acch);
      __syncthreads();
      load_A(par, 3, 1); cpa_commit();

      // chunk 2
      cpa_wait<1>(); __syncthreads();
#pragma unroll
      for (int b = 0; b < 4; b++)
        compute_blk_ldsm(sA + (unsigned)(0*18432 + b*4608)*2 + aoff,
                         cbB + (unsigned)((2*4+b)*1152)*2,
                         hbB + (unsigned)((2*4+b)*1152)*2, accc, acch);

      // chunk 3 (wait<0> also covers next-stage B)
      cpa_wait<0>(); __syncthreads();
#pragma unroll
      for (int b = 0; b < 4; b++)
        compute_blk_ldsm(sA + (unsigned)(1*18432 + b*4608)*2 + aoff,
                         cbB + (unsigned)((3*4+b)*1152)*2,
                         hbB + (unsigned)((3*4+b)*1152)*2, accc, acch);

      // fused epilogue
      {
        const int np = par ^ 1;
        __half* Hh16 = g_Hh2 + (size_t)np*Bb*Hh;

        float sc0=accc[0], sc1=accc[1], sc2=accc[2], sc3=accc[3];
        float sh0=acch[0], sh1=acch[1], sh2=acch[2], sh3=acch[3];
        if (s == 0){
          const float* XCb = g_XC + ((size_t)t<<17);
          const float* XHb = g_XH + ((size_t)t<<17);
          float2 a0 = *(const float2*)(XCb + (size_t)r0*Hh + c0);
          float2 a1 = *(const float2*)(XCb + (size_t)r1*Hh + c0);
          float2 b0 = *(const float2*)(XHb + (size_t)r0*Hh + c0);
          float2 b1 = *(const float2*)(XHb + (size_t)r1*Hh + c0);
          sc0 += a0.x; sc1 += a0.y; sc2 += a1.x; sc3 += a1.y;
          sh0 += b0.x; sh1 += b0.y; sh2 += b1.x; sh3 += b1.y;
        }
        const bool use_tanh = (s == 0) || (s & 1);
        float g0 = sigm(sc0), g1 = sigm(sc1), g2 = sigm(sc2), g3 = sigm(sc3);
        float a0 = use_tanh ? tanhf(sh0) : fmaxf(sh0, 0.f);
        float a1 = use_tanh ? tanhf(sh1) : fmaxf(sh1, 0.f);
        float a2 = use_tanh ? tanhf(sh2) : fmaxf(sh2, 0.f);
        float a3 = use_tanh ? tanhf(sh3) : fmaxf(sh3, 0.f);
        float n0v = g0*a0 + (1.f-g0)*hp0;
        float n1v = g1*a1 + (1.f-g1)*hp1;
        float n2v = g2*a2 + (1.f-g2)*hp2;
        float n3v = g3*a3 + (1.f-g3)*hp3;

        if (s < NBLK-1){
          hp0 = n0v; hp1 = n1v; hp2 = n2v; hp3 = n3v;
          __half2 p0 = __floats2half2_rn(n0v, n1v);
          __half2 p1 = __floats2half2_rn(n2v, n3v);
          *(unsigned*)(Hh16 + (size_t)r0*Hh + c0) = *(unsigned*)&p0;
          *(unsigned*)(Hh16 + (size_t)r1*Hh + c0) = *(unsigned*)&p1;
        } else {
          float* Ob = g_OUT + ((size_t)t<<17);
          *(float2*)(Ob + (size_t)r0*Hh + c0) = make_float2(rndtf(n0v), rndtf(n1v));
          *(float2*)(Ob + (size_t)r1*Hh + c0) = make_float2(rndtf(n2v), rndtf(n3v));
          float ss0 = n0v*n0v + n1v*n1v;
          float ss1 = n2v*n2v + n3v*n3v;
          ss0 += __shfl_xor_sync(0xffffffffu, ss0, 1);
          ss0 += __shfl_xor_sync(0xffffffffu, ss0, 2);
          ss1 += __shfl_xor_sync(0xffffffffu, ss1, 1);
          ss1 += __shfl_xor_sync(0xffffffffu, ss1, 2);
          if (tg == 0){
            g_pss[r0*128 + nt*2 + wni] = ss0;
            g_pss[r1*128 + nt*2 + wni] = ss1;
          }
          gsyncg(ep, mrow, nt);
          float t0 = 0.f, t1 = 0.f;
          const float4* q0 = (const float4*)(g_pss + (size_t)r0*128);
          const float4* q1 = (const float4*)(g_pss + (size_t)r1*128);
#pragma unroll
          for (int j = 0; j < 32; j++){
            float4 v = q0[j]; t0 += v.x + v.y + v.z + v.w;
            float4 w = q1[j]; t1 += w.x + w.y + w.z + w.w;
          }
          float nm0 = sqrtf(t0), nm1 = sqrtf(t1);
          float sA0 = (nm0 > 25.f) ? (25.f / nm0) : 1.f;
          float sA1 = (nm1 > 25.f) ? (25.f / nm1) : 1.f;
          hp0 = n0v * sA0; hp1 = n1v * sA0;
          hp2 = n2v * sA1; hp3 = n3v * sA1;
          __half2 p0 = __floats2half2_rn(hp0, hp1);
          __half2 p1 = __floats2half2_rn(hp2, hp3);
          *(unsigned*)(Hh16 + (size_t)r0*Hh + c0) = *(unsigned*)&p0;
          *(unsigned*)(Hh16 + (size_t)r1*Hh + c0) = *(unsigned*)&p1;
        }
      }
      gsyncg(ep, mrow, nt);
    }
  }

  // hT (clipped final hidden, from registers)
  {
    float* o = outp + (size_t)Tt*Bb*Vv;
    *(float2*)(o + (size_t)r0*Hh + c0) = make_float2(hp0, hp1);
    *(float2*)(o + (size_t)r1*Hh + c0) = make_float2(hp2, hp3);
  }
}

// ---------------- phase 3: decoder GEMM (tf32, PIPE=2, 3 CTAs/SM) ----------------
__global__ void __launch_bounds__(256) dec_kernel(
  const float* __restrict__ decB, float* __restrict__ outp)
{
  extern __shared__ unsigned char smraw[];
  float* Ash = (float*)smraw;
  float* Bsh = (float*)smraw + PIPE*4608;
  const int tid = threadIdx.x;
  const int n0 = blockIdx.x * 128;
  const int m0 = blockIdx.y * 128;
  const int lane = tid & 31, warp = tid >> 5;
  const int wm = (warp & 1) * 64, wn = (warp >> 1) * 32;
  const int g = lane >> 2, tg = lane & 3;
  float acc[4][4][4];
#pragma unroll
  for (int a=0;a<4;a++)
#pragma unroll
    for (int b=0;b<4;b++)
#pragma unroll
      for (int c=0;c<4;c++) acc[a][b][c]=0.f;

  auto load_tile = [&](int p, int kbi){
    int kb = kbi * 32;
#pragma unroll
    for (int i = 0; i < 4; i++){
      int idx = tid + i*256, row = idx>>3, c4 = (idx&7)*4;
      cpa16(&Ash[p*4608 + row*36 + c4], g_OUT + (size_t)(m0+row)*Hh + kb + c4);
      cpa16(&Bsh[p*4608 + row*36 + c4], g_Wd + (size_t)(n0+row)*Hh + kb + c4);
    }
  };

#pragma unroll
  for (int p = 0; p < PIPE-1; p++){ load_tile(p, p); cpa_commit(); }
  for (int it = 0; it < 32; it++){
    cpa_wait<PIPE-2>();
    __syncthreads();
    int nx = it + PIPE - 1;
    if (nx < 32) load_tile(nx % PIPE, nx);
    cpa_commit();
    compute_64x32(Ash + (it%PIPE)*4608, Bsh + (it%PIPE)*4608, acc, wm, wn, g, tg);
  }

#pragma unroll
  for (int mi=0;mi<4;mi++){
    int r = m0 + wm + mi*16 + g;
#pragma unroll
    for (int ni=0;ni<4;ni++){
      int c = n0 + wn + ni*8 + 2*tg;
      if (c < Vv){
        float b0 = decB[c], b1 = decB[c+1];
        size_t o  = (size_t)r*Vv + c;
        size_t o2 = o + (size_t)8*Vv;
        outp[o]    = acc[mi][ni][0] + b0;
        outp[o+1]  = acc[mi][ni][1] + b1;
        outp[o2]   = acc[mi][ni][2] + b0;
        outp[o2+1] = acc[mi][ni][3] + b1;
      }
    }
  }
}

// ---------------- launch ----------------
extern "C" void kernel_launch(void* const* d_in, const int* in_sizes, int n_in,
                              void* d_out, int out_size){
  const int*   tokens = (const int*)  d_in[0];
  const float* embW   = (const float*)d_in[1];
  const float* wxcW   = (const float*)d_in[2];
  const float* wxcB   = (const float*)d_in[3];
  const float* wxhW   = (const float*)d_in[4];
  const float* wxhB   = (const float*)d_in[5];
  const float* w_hc   = (const float*)d_in[6];
  const float* w_hh   = (const float*)d_in[7];
  const float* edge_h = (const float*)d_in[8];
  const float* edge_c = (const float*)d_in[9];
  const float* decW   = (const float*)d_in[10];
  const float* decB   = (const float*)d_in[11];
  float* outp = (float*)d_out;
  (void)in_sizes; (void)n_in; (void)out_size;

  const int RNN_SMEM  = (2*18432 + 2*36864) * 2;   // 221184 B
  const int GEMM_SMEM = PIPE * 2 * 4608 * 4;       // 73728 B -> 3 CTAs/SM
  cudaFuncSetAttribute(xproj_kernel, cudaFuncAttributeMaxDynamicSharedMemorySize, GEMM_SMEM);
  cudaFuncSetAttribute(rnn_kernel,   cudaFuncAttributeMaxDynamicSharedMemorySize, RNN_SMEM);
  cudaFuncSetAttribute(dec_kernel,   cudaFuncAttributeMaxDynamicSharedMemorySize, GEMM_SMEM);

  // reset barrier flags
  void *pArr = nullptr, *pRel = nullptr;
  cudaGetSymbolAddress(&pArr, g_arr);
  cudaGetSymbolAddress(&pRel, g_rel2);
  cudaMemsetAsync(pArr, 0, sizeof(unsigned)*GRID_R);
  cudaMemsetAsync(pRel, 0, sizeof(unsigned)*2);

  const long PREP_TOTAL = S_WC + S_WH + S_WE + S_WX + S_WD;
  prep_all<<<(unsigned)((PREP_TOTAL + 255) / 256), 256>>>(
      w_hc, edge_c, w_hh, edge_h, embW, wxcW, wxhW, decW);

  xproj_kernel<<<dim3(8, 64, 2), 256, GEMM_SMEM>>>(tokens, wxcB, wxhB);
  rnn_kernel<<<GRID_R, 256, RNN_SMEM>>>(outp);
  dec_kernel<<<dim3(VPAD/128, 64), 256, GEMM_SMEM>>>(decB, outp);
}